// round 10
// baseline (speedup 1.0000x reference)
#include <cuda_runtime.h>
#include <cuda_fp16.h>
#include <math.h>
#include <stdint.h>

#define B_    2
#define S_    2048
#define HID_  1024
#define NH_   16
#define HD_   64
#define MTOT  (B_ * S_)
#define WN_   (HID_ * HID_)
#define LOG2E 1.4426950408889634f

// ---------------- scratch (static device allocations) ----------------
__device__ __half g_Xh[MTOT * HID_];
__device__ __half g_Wh[4 * WN_];
__device__ __half g_Q[MTOT * HID_];
__device__ __half g_K[MTOT * HID_];
__device__ __half g_V[MTOT * HID_];
__device__ __half g_Ch[MTOT * HID_];
__device__ __half g_Cl[MTOT * HID_];
__device__ float  g_Madd[MTOT];

// ---------------- helpers (baseline PTX only) ----------------
__device__ __forceinline__ uint32_t smem_u32(const void* p) {
    uint32_t a;
    asm("{ .reg .u64 t; cvta.to.shared.u64 t, %1; cvt.u32.u64 %0, t; }" : "=r"(a) : "l"(p));
    return a;
}
__device__ __forceinline__ void ldsm_x4(uint32_t addr, uint32_t& r0, uint32_t& r1,
                                        uint32_t& r2, uint32_t& r3) {
    asm volatile("ldmatrix.sync.aligned.m8n8.x4.shared.b16 {%0,%1,%2,%3}, [%4];"
                 : "=r"(r0), "=r"(r1), "=r"(r2), "=r"(r3) : "r"(addr));
}
__device__ __forceinline__ void ldsm_x4_trans(uint32_t addr, uint32_t& r0, uint32_t& r1,
                                              uint32_t& r2, uint32_t& r3) {
    asm volatile("ldmatrix.sync.aligned.m8n8.x4.trans.shared.b16 {%0,%1,%2,%3}, [%4];"
                 : "=r"(r0), "=r"(r1), "=r"(r2), "=r"(r3) : "r"(addr));
}
__device__ __forceinline__ void mma16816(float* c, uint32_t a0, uint32_t a1,
                                         uint32_t a2, uint32_t a3,
                                         uint32_t b0, uint32_t b1) {
    asm volatile(
        "mma.sync.aligned.m16n8k16.row.col.f32.f16.f16.f32 "
        "{%0,%1,%2,%3}, {%4,%5,%6,%7}, {%8,%9}, {%0,%1,%2,%3};"
        : "+f"(c[0]), "+f"(c[1]), "+f"(c[2]), "+f"(c[3])
        : "r"(a0), "r"(a1), "r"(a2), "r"(a3), "r"(b0), "r"(b1));
}
__device__ __forceinline__ uint32_t pack_h2(float a, float b) {
    __half2 h = __floats2half2_rn(a, b);
    return *(uint32_t*)&h;
}
__device__ __forceinline__ void pack2_hilo(float a, float b, uint32_t& hi, uint32_t& lo) {
    __half2 h = __floats2half2_rn(a, b);
    float2 hf = __half22float2(h);
    __half2 l = __floats2half2_rn(a - hf.x, b - hf.y);
    hi = *(uint32_t*)&h;
    lo = *(uint32_t*)&l;
}
#define CP16(dst, src) \
    asm volatile("cp.async.cg.shared.global [%0], [%1], 16;" :: "r"(dst), "l"(src))
#define CP_COMMIT() asm volatile("cp.async.commit_group;")
#define CP_WAIT1()  asm volatile("cp.async.wait_group 1;")

// ---------------- converters ----------------
__global__ __launch_bounds__(256) void cvt_h(
    const float* __restrict__ in, __half* __restrict__ outp, int n4)
{
    int i = blockIdx.x * blockDim.x + threadIdx.x;
    if (i >= n4) return;
    float4 v = ((const float4*)in)[i];
    ((uint2*)outp)[i] = make_uint2(pack_h2(v.x, v.y), pack_h2(v.z, v.w));
}

__global__ __launch_bounds__(256) void cvt_h4(
    const float* __restrict__ w0, const float* __restrict__ w1,
    const float* __restrict__ w2, const float* __restrict__ w3,
    __half* __restrict__ wh)
{
    const int n4per = WN_ / 4;
    int i = blockIdx.x * blockDim.x + threadIdx.x;
    int sel = i / n4per;
    int j   = i - sel * n4per;
    const float* src = sel == 0 ? w0 : (sel == 1 ? w1 : (sel == 2 ? w2 : w3));
    float4 v = ((const float4*)src)[j];
    ((uint2*)wh)[i] = make_uint2(pack_h2(v.x, v.y), pack_h2(v.z, v.w));
}

// mask -> additive log2-domain term: (1-mask)*(-10000)*log2e
__global__ __launch_bounds__(256) void msk_prep(
    const float* __restrict__ mask, float* __restrict__ madd, int n)
{
    int i = blockIdx.x * blockDim.x + threadIdx.x;
    if (i >= n) return;
    madd[i] = (1.0f - mask[i]) * (-10000.0f * LOG2E);
}

// ============================================================
// Tensor-core GEMM, cp.async double-buffered.
// TWOTERM: C = ((Ahi+Alo) @ W^T + bias)*osc ;  else single-A.
// grid.z selects among up to 3 (W, bias, dest) sets.
// ============================================================
#define LDA 40
#define G_AS (128 * LDA)

template<bool OUT16, bool TWOTERM>
__global__ __launch_bounds__(256) void gemm_mma_f16(
    const __half* __restrict__ Ahi, const __half* __restrict__ Alo,
    const __half* __restrict__ Whb,
    const float* __restrict__ bias0, const float* __restrict__ bias1,
    const float* __restrict__ bias2,
    float* __restrict__ C,
    __half* __restrict__ C0, __half* __restrict__ C1, __half* __restrict__ C2,
    int M, int N, int K, float osc0, float osc12)
{
    constexpr int NARR = TWOTERM ? 3 : 2;
    constexpr uint32_t STAGE_B = NARR * G_AS * 2;
    extern __shared__ char smem[];
    const uint32_t sb = smem_u32(smem);

    const int z = blockIdx.z;
    const __half* Bh = Whb + (size_t)z * WN_;
    const float* bias = z == 0 ? bias0 : (z == 1 ? bias1 : bias2);
    __half* Cd = z == 0 ? C0 : (z == 1 ? C1 : C2);
    const float oscale = z == 0 ? osc0 : osc12;

    const int t    = threadIdx.x;
    const int lane = t & 31;
    const int wid  = t >> 5;
    const int wm   = (wid & 1) * 64;
    const int wn   = (wid >> 1) * 32;
    const int bm   = blockIdx.y * 128;
    const int bn   = blockIdx.x * 128;

    float acc[4][4][4];
#pragma unroll
    for (int i = 0; i < 4; i++)
#pragma unroll
        for (int j = 0; j < 4; j++)
#pragma unroll
            for (int r = 0; r < 4; r++) acc[i][j][r] = 0.0f;

    const int lr = t >> 2;
    const int lc = (t & 3) * 8;

    const uint32_t aOff = (uint32_t)(((wm + (lane & 15)) * LDA + (lane >> 4) * 8) * 2);
    const uint32_t bOff = (uint32_t)(((wn + (lane >> 4) * 8 + (lane & 7)) * LDA + ((lane >> 3) & 1) * 8) * 2);

#define G_LOAD(s, k0) do {                                                        \
        uint32_t st = sb + (uint32_t)(s) * STAGE_B;                               \
        _Pragma("unroll")                                                         \
        for (int bch = 0; bch < 2; bch++) {                                       \
            int r = lr + bch * 64;                                                \
            size_t ga = (size_t)(bm + r) * K + (k0) + lc;                         \
            size_t gb = (size_t)(bn + r) * K + (k0) + lc;                         \
            uint32_t so = (uint32_t)((r * LDA + lc) * 2);                         \
            CP16(st + 0 * G_AS * 2 + so, Ahi + ga);                               \
            if (TWOTERM) CP16(st + 1 * G_AS * 2 + so, Alo + ga);                  \
            CP16(st + (NARR - 1) * G_AS * 2 + so, Bh + gb);                       \
        }                                                                         \
    } while (0)

    const int NK = K / 32;
    G_LOAD(0, 0);
    CP_COMMIT();

    for (int it = 0; it < NK; it++) {
        if (it + 1 < NK) G_LOAD((it + 1) & 1, (it + 1) * 32);
        CP_COMMIT();
        CP_WAIT1();
        __syncthreads();

        const uint32_t st  = sb + (uint32_t)(it & 1) * STAGE_B;
        const uint32_t aB  = st;
        const uint32_t alB = st + 1 * G_AS * 2;
        const uint32_t bB  = st + (NARR - 1) * G_AS * 2;

#pragma unroll
        for (int ks = 0; ks < 2; ks++) {
            const uint32_t kb = ks * 32;
            uint32_t bh[8];
#pragma unroll
            for (int pr = 0; pr < 2; pr++) {
                uint32_t ba = bOff + (uint32_t)(pr * 16 * LDA * 2) + kb;
                ldsm_x4(bB + ba, bh[pr*4+0], bh[pr*4+1], bh[pr*4+2], bh[pr*4+3]);
            }
            uint32_t ah[4][4], al[4][4];
#pragma unroll
            for (int mt = 0; mt < 4; mt++) {
                uint32_t aa = aOff + (uint32_t)(mt * 16 * LDA * 2) + kb;
                ldsm_x4(aB + aa, ah[mt][0], ah[mt][1], ah[mt][2], ah[mt][3]);
                if (TWOTERM)
                    ldsm_x4(alB + aa, al[mt][0], al[mt][1], al[mt][2], al[mt][3]);
            }
#pragma unroll
            for (int mt = 0; mt < 4; mt++) {
#pragma unroll
                for (int nt = 0; nt < 4; nt++) {
                    const int pr = nt >> 1, hf = (nt & 1) * 2;
                    uint32_t b0 = bh[pr*4 + hf], b1 = bh[pr*4 + hf + 1];
                    mma16816(acc[mt][nt], ah[mt][0], ah[mt][1], ah[mt][2], ah[mt][3], b0, b1);
                    if (TWOTERM)
                        mma16816(acc[mt][nt], al[mt][0], al[mt][1], al[mt][2], al[mt][3], b0, b1);
                }
            }
        }
        __syncthreads();
    }

#pragma unroll
    for (int mt = 0; mt < 4; mt++) {
#pragma unroll
        for (int nt = 0; nt < 4; nt++) {
            int row = bm + wm + mt * 16 + (lane >> 2);
            int col = bn + wn + nt * 8 + (lane & 3) * 2;
            float2 bvv = *(const float2*)&bias[col];
            float v0x = (acc[mt][nt][0] + bvv.x) * oscale, v0y = (acc[mt][nt][1] + bvv.y) * oscale;
            float v1x = (acc[mt][nt][2] + bvv.x) * oscale, v1y = (acc[mt][nt][3] + bvv.y) * oscale;
            if (OUT16) {
                *(uint32_t*)&Cd[(size_t)row * N + col]       = pack_h2(v0x, v0y);
                *(uint32_t*)&Cd[(size_t)(row + 8) * N + col] = pack_h2(v1x, v1y);
            } else {
                *(float2*)&C[(size_t)row * N + col] = make_float2(v0x, v0y);
                *(float2*)&C[(size_t)(row + 8) * N + col] = make_float2(v1x, v1y);
            }
        }
    }
}

// ============================================================
// Tensor-core flash ConsMax attention, single fp16, exp2 domain.
// Q pre-scaled by log2e/8 upstream; mask pre-scaled by log2e.
// QK^T = 1 MMA, PV = 1 MMA. 128 q-rows/CTA, 8 warps, Bc=64.
// ============================================================
#define LDV 72
#define A_AS (64 * LDV)
#define A_STAGE_B (2 * A_AS * 2)
#define A_MASK_OFF (2 * A_STAGE_B)
#define A_SMEM_B (A_MASK_OFF + 2 * 256)

__global__ __launch_bounds__(256) void consmax_attn_mma(
    const __half* __restrict__ Q, const __half* __restrict__ K,
    const __half* __restrict__ V,
    const float* __restrict__ madd, const float* __restrict__ gamma,
    __half* __restrict__ Ch, __half* __restrict__ Cl)
{
    extern __shared__ char smem[];
    const uint32_t sb = smem_u32(smem);

    const int qb = blockIdx.x, h = blockIdx.y, b = blockIdx.z;
    const int t = threadIdx.x, lane = t & 31, w = t >> 5;
    const int row0 = b * S_ + qb * 128;

    // ---- Q fragments straight from global (A-frag layout) ----
    uint32_t qf[4][4];
    {
        const int fr = lane >> 2;
        const int fc = (lane & 3) * 2;
        const size_t base = (size_t)(row0 + w * 16 + fr) * HID_ + h * HD_ + fc;
#pragma unroll
        for (int ks = 0; ks < 4; ks++) {
            const size_t g = base + ks * 16;
            qf[ks][0] = *(const uint32_t*)(Q + g);
            qf[ks][1] = *(const uint32_t*)(Q + g + 8 * HID_);
            qf[ks][2] = *(const uint32_t*)(Q + g + 8);
            qf[ks][3] = *(const uint32_t*)(Q + g + 8 * HID_ + 8);
        }
    }

    float m0 = -1e30f, m1 = -1e30f;
    float O[8][4];
#pragma unroll
    for (int nt = 0; nt < 8; nt++)
#pragma unroll
        for (int r = 0; r < 4; r++) O[nt][r] = 0.0f;

#define A_LOAD(s, j0) do {                                                        \
        uint32_t st = sb + (uint32_t)(s) * A_STAGE_B;                             \
        _Pragma("unroll")                                                         \
        for (int i2 = 0; i2 < 2; i2++) {                                          \
            int u = t + 256 * i2;                                                 \
            int r = u >> 3, seg = u & 7;                                          \
            const size_t g = (size_t)(b * S_ + (j0) + r) * HID_ + h * HD_ + seg * 8; \
            uint32_t so = (uint32_t)((r * LDV + seg * 8) * 2);                    \
            CP16(st + 0 * A_AS * 2 + so, K + g);                                  \
            CP16(st + 1 * A_AS * 2 + so, V + g);                                  \
        }                                                                         \
        if (t < 16)                                                               \
            CP16(sb + A_MASK_OFF + (uint32_t)(s) * 256 + t * 16,                  \
                 madd + (size_t)b * S_ + (j0) + t * 4);                           \
    } while (0)

    const int NCH = S_ / 64;
    A_LOAD(0, 0);
    CP_COMMIT();

    for (int it = 0; it < NCH; it++) {
        if (it + 1 < NCH) A_LOAD((it + 1) & 1, (it + 1) * 64);
        CP_COMMIT();
        CP_WAIT1();
        __syncthreads();

        const uint32_t st  = sb + (uint32_t)(it & 1) * A_STAGE_B;
        const uint32_t kB  = st;
        const uint32_t vB  = st + 1 * A_AS * 2;
        const float* smask = (const float*)(smem + A_MASK_OFF + (it & 1) * 256);

        // ---- S2 = log2e * (Q K^T)/8  (scale folded into Q) ----
        float sc[8][4];
#pragma unroll
        for (int nt = 0; nt < 8; nt++)
#pragma unroll
            for (int r = 0; r < 4; r++) sc[nt][r] = 0.0f;

#pragma unroll
        for (int ks = 0; ks < 4; ks++) {
            uint32_t bh[4][4];
#pragma unroll
            for (int nb = 0; nb < 4; nb++) {
                uint32_t addr = (uint32_t)(((nb * 16 + (lane >> 4) * 8 + (lane & 7)) * LDV
                                            + ks * 16 + ((lane >> 3) & 1) * 8) * 2);
                ldsm_x4(kB + addr, bh[nb][0], bh[nb][1], bh[nb][2], bh[nb][3]);
            }
#pragma unroll
            for (int nb = 0; nb < 4; nb++) {
                mma16816(sc[2*nb],   qf[ks][0], qf[ks][1], qf[ks][2], qf[ks][3], bh[nb][0], bh[nb][1]);
                mma16816(sc[2*nb+1], qf[ks][0], qf[ks][1], qf[ks][2], qf[ks][3], bh[nb][2], bh[nb][3]);
            }
        }

        // ---- mask + running rowmax (log2 domain) ----
        float mn0 = m0, mn1 = m1;
#pragma unroll
        for (int nt = 0; nt < 8; nt++) {
            int col = nt * 8 + (lane & 3) * 2;
            float ma = smask[col], mb2 = smask[col + 1];
            sc[nt][0] += ma; sc[nt][1] += mb2;
            sc[nt][2] += ma; sc[nt][3] += mb2;
            mn0 = fmaxf(mn0, fmaxf(sc[nt][0], sc[nt][1]));
            mn1 = fmaxf(mn1, fmaxf(sc[nt][2], sc[nt][3]));
        }
        mn0 = fmaxf(mn0, __shfl_xor_sync(0xffffffffu, mn0, 1));
        mn0 = fmaxf(mn0, __shfl_xor_sync(0xffffffffu, mn0, 2));
        mn1 = fmaxf(mn1, __shfl_xor_sync(0xffffffffu, mn1, 1));
        mn1 = fmaxf(mn1, __shfl_xor_sync(0xffffffffu, mn1, 2));
        float f0 = exp2f(m0 - mn0), f1 = exp2f(m1 - mn1);
        m0 = mn0; m1 = mn1;

        // ---- P = exp2(s2 - m2) as single fp16 A-frags ----
        uint32_t pa[4][4];
#pragma unroll
        for (int ks = 0; ks < 4; ks++) {
            pa[ks][0] = pack_h2(exp2f(sc[2*ks][0] - m0),   exp2f(sc[2*ks][1] - m0));
            pa[ks][1] = pack_h2(exp2f(sc[2*ks][2] - m1),   exp2f(sc[2*ks][3] - m1));
            pa[ks][2] = pack_h2(exp2f(sc[2*ks+1][0] - m0), exp2f(sc[2*ks+1][1] - m0));
            pa[ks][3] = pack_h2(exp2f(sc[2*ks+1][2] - m1), exp2f(sc[2*ks+1][3] - m1));
        }

        // ---- rescale O ----
#pragma unroll
        for (int nt = 0; nt < 8; nt++) {
            O[nt][0] *= f0; O[nt][1] *= f0; O[nt][2] *= f1; O[nt][3] *= f1;
        }

        // ---- O += P V (1 MMA per tile) ----
#pragma unroll
        for (int ks = 0; ks < 4; ks++) {
            uint32_t vf[4][4];
#pragma unroll
            for (int db = 0; db < 4; db++) {
                uint32_t addr = (uint32_t)(((ks * 16 + ((lane >> 3) & 1) * 8 + (lane & 7)) * LDV
                                            + db * 16 + (lane >> 4) * 8) * 2);
                ldsm_x4_trans(vB + addr, vf[db][0], vf[db][1], vf[db][2], vf[db][3]);
            }
#pragma unroll
            for (int db = 0; db < 4; db++) {
                mma16816(O[2*db],   pa[ks][0], pa[ks][1], pa[ks][2], pa[ks][3], vf[db][0], vf[db][1]);
                mma16816(O[2*db+1], pa[ks][0], pa[ks][1], pa[ks][2], pa[ks][3], vf[db][2], vf[db][3]);
            }
        }
        __syncthreads();
    }

    // ---- epilogue: O/gamma -> fp16 hi/lo ----
    const float ig = 1.0f / gamma[0];
#pragma unroll
    for (int nt = 0; nt < 8; nt++) {
        int r = row0 + w * 16 + (lane >> 2);
        int col = h * HD_ + nt * 8 + (lane & 3) * 2;
        uint32_t h0, l0, h1, l1;
        pack2_hilo(O[nt][0] * ig, O[nt][1] * ig, h0, l0);
        pack2_hilo(O[nt][2] * ig, O[nt][3] * ig, h1, l1);
        *(uint32_t*)&Ch[(size_t)r * HID_ + col] = h0;
        *(uint32_t*)&Cl[(size_t)r * HID_ + col] = l0;
        *(uint32_t*)&Ch[(size_t)(r + 8) * HID_ + col] = h1;
        *(uint32_t*)&Cl[(size_t)(r + 8) * HID_ + col] = l1;
    }
}

// ============================================================
// Launch
// ============================================================
extern "C" void kernel_launch(void* const* d_in, const int* in_sizes, int n_in,
                              void* d_out, int out_size)
{
    (void)in_sizes; (void)n_in; (void)out_size;
    const float* X    = (const float*)d_in[0];
    const float* mask = (const float*)d_in[1];
    const float* Wq   = (const float*)d_in[2];
    const float* bq   = (const float*)d_in[3];
    const float* Wk   = (const float*)d_in[4];
    const float* bk   = (const float*)d_in[5];
    const float* Wv   = (const float*)d_in[6];
    const float* bv   = (const float*)d_in[7];
    const float* Wo   = (const float*)d_in[8];
    const float* bo   = (const float*)d_in[9];
    const float* gamma = (const float*)d_in[11];   // beta (d_in[10]) cancels exactly
    float* out = (float*)d_out;

    __half *xh, *wh, *qp, *kp, *vp, *chp, *clp;
    float* mad;
    cudaGetSymbolAddress((void**)&xh,  g_Xh);
    cudaGetSymbolAddress((void**)&wh,  g_Wh);
    cudaGetSymbolAddress((void**)&qp,  g_Q);
    cudaGetSymbolAddress((void**)&kp,  g_K);
    cudaGetSymbolAddress((void**)&vp,  g_V);
    cudaGetSymbolAddress((void**)&chp, g_Ch);
    cudaGetSymbolAddress((void**)&clp, g_Cl);
    cudaGetSymbolAddress((void**)&mad, g_Madd);

    const int G_SMEM1 = 2 * (2 * G_AS * 2);   // single-A stages
    const int G_SMEM2 = 2 * (3 * G_AS * 2);   // two-term stages
    cudaFuncSetAttribute((const void*)gemm_mma_f16<true, false>,
                         cudaFuncAttributeMaxDynamicSharedMemorySize, G_SMEM1);
    cudaFuncSetAttribute((const void*)gemm_mma_f16<false, true>,
                         cudaFuncAttributeMaxDynamicSharedMemorySize, G_SMEM2);
    cudaFuncSetAttribute((const void*)consmax_attn_mma,
                         cudaFuncAttributeMaxDynamicSharedMemorySize, A_SMEM_B);

    cvt_h<<<(MTOT * HID_ / 4 + 255) / 256, 256>>>(X, xh, MTOT * HID_ / 4);
    cvt_h4<<<(4 * WN_ / 4) / 256, 256>>>(Wq, Wk, Wv, Wo, wh);
    msk_prep<<<(MTOT + 255) / 256, 256>>>(mask, mad, MTOT);

    // fused QKV projection (single-A): z = 0(Q, x log2e/8), 1(K), 2(V)
    dim3 gq(HID_ / 128, MTOT / 128, 3);
    gemm_mma_f16<true, false><<<gq, 256, G_SMEM1>>>(xh, nullptr, wh,
                                                    bq, bk, bv, nullptr,
                                                    qp, kp, vp,
                                                    MTOT, HID_, HID_,
                                                    0.125f * LOG2E, 1.0f);

    dim3 ga(S_ / 128, NH_, B_);        // (16, 16, 2)
    consmax_attn_mma<<<ga, 256, A_SMEM_B>>>(qp, kp, vp, mad, gamma, chp, clp);

    // output projection (two-term C hi/lo)
    dim3 go(HID_ / 128, MTOT / 128, 1);
    gemm_mma_f16<false, true><<<go, 256, G_SMEM2>>>(chp, clp, wh + 3 * (size_t)WN_,
                                                    bo, nullptr, nullptr,
                                                    out, nullptr, nullptr, nullptr,
                                                    MTOT, HID_, HID_, 1.0f, 1.0f);
}

// round 11
// speedup vs baseline: 1.2931x; 1.2931x over previous
#include <cuda_runtime.h>
#include <cuda_fp16.h>
#include <math.h>
#include <stdint.h>

#define B_    2
#define S_    2048
#define HID_  1024
#define NH_   16
#define HD_   64
#define MTOT  (B_ * S_)
#define WN_   (HID_ * HID_)

// ---------------- scratch (static device allocations) ----------------
__device__ __half g_Xhi[MTOT * HID_];
__device__ __half g_Xlo[MTOT * HID_];
__device__ __half g_Wh[4 * WN_];
__device__ __half g_Q[MTOT * HID_];
__device__ __half g_K[MTOT * HID_];
__device__ __half g_V[MTOT * HID_];
__device__ __half g_Ch[MTOT * HID_];
__device__ __half g_Cl[MTOT * HID_];

// ---------------- helpers (baseline PTX only) ----------------
__device__ __forceinline__ uint32_t smem_u32(const void* p) {
    uint32_t a;
    asm("{ .reg .u64 t; cvta.to.shared.u64 t, %1; cvt.u32.u64 %0, t; }" : "=r"(a) : "l"(p));
    return a;
}
__device__ __forceinline__ void ldsm_x4(uint32_t addr, uint32_t& r0, uint32_t& r1,
                                        uint32_t& r2, uint32_t& r3) {
    asm volatile("ldmatrix.sync.aligned.m8n8.x4.shared.b16 {%0,%1,%2,%3}, [%4];"
                 : "=r"(r0), "=r"(r1), "=r"(r2), "=r"(r3) : "r"(addr));
}
__device__ __forceinline__ void ldsm_x4_trans(uint32_t addr, uint32_t& r0, uint32_t& r1,
                                              uint32_t& r2, uint32_t& r3) {
    asm volatile("ldmatrix.sync.aligned.m8n8.x4.trans.shared.b16 {%0,%1,%2,%3}, [%4];"
                 : "=r"(r0), "=r"(r1), "=r"(r2), "=r"(r3) : "r"(addr));
}
__device__ __forceinline__ void mma16816(float* c, uint32_t a0, uint32_t a1,
                                         uint32_t a2, uint32_t a3,
                                         uint32_t b0, uint32_t b1) {
    asm volatile(
        "mma.sync.aligned.m16n8k16.row.col.f32.f16.f16.f32 "
        "{%0,%1,%2,%3}, {%4,%5,%6,%7}, {%8,%9}, {%0,%1,%2,%3};"
        : "+f"(c[0]), "+f"(c[1]), "+f"(c[2]), "+f"(c[3])
        : "r"(a0), "r"(a1), "r"(a2), "r"(a3), "r"(b0), "r"(b1));
}
__device__ __forceinline__ uint32_t pack_h2(float a, float b) {
    __half2 h = __floats2half2_rn(a, b);
    return *(uint32_t*)&h;
}
__device__ __forceinline__ void pack2_hilo(float a, float b, uint32_t& hi, uint32_t& lo) {
    __half2 h = __floats2half2_rn(a, b);
    float2 hf = __half22float2(h);
    __half2 l = __floats2half2_rn(a - hf.x, b - hf.y);
    hi = *(uint32_t*)&h;
    lo = *(uint32_t*)&l;
}
#define CP16(dst, src) \
    asm volatile("cp.async.cg.shared.global [%0], [%1], 16;" :: "r"(dst), "l"(src))
#define CP_COMMIT() asm volatile("cp.async.commit_group;")
#define CP_WAIT1()  asm volatile("cp.async.wait_group 1;")

// ---------------- converters ----------------
__global__ __launch_bounds__(256) void cvt_split(
    const float* __restrict__ in, __half* __restrict__ hi,
    __half* __restrict__ lo, int n4)
{
    int i = blockIdx.x * blockDim.x + threadIdx.x;
    if (i >= n4) return;
    float4 v = ((const float4*)in)[i];
    uint32_t h0, l0, h1, l1;
    pack2_hilo(v.x, v.y, h0, l0);
    pack2_hilo(v.z, v.w, h1, l1);
    ((uint2*)hi)[i] = make_uint2(h0, h1);
    ((uint2*)lo)[i] = make_uint2(l0, l1);
}

__global__ __launch_bounds__(256) void cvt_h4(
    const float* __restrict__ w0, const float* __restrict__ w1,
    const float* __restrict__ w2, const float* __restrict__ w3,
    __half* __restrict__ wh)
{
    const int n4per = WN_ / 4;
    int i = blockIdx.x * blockDim.x + threadIdx.x;
    int sel = i / n4per;
    int j   = i - sel * n4per;
    const float* src = sel == 0 ? w0 : (sel == 1 ? w1 : (sel == 2 ? w2 : w3));
    float4 v = ((const float4*)src)[j];
    ((uint2*)wh)[i] = make_uint2(pack_h2(v.x, v.y), pack_h2(v.z, v.w));
}

// ============================================================
// Tensor-core GEMM, 3-stage cp.async pipeline, 1 sync/iter.
// fp16 2-term: C = ((Ahi+Alo) @ W^T + bias) * oscale.
// grid.z selects among up to 3 (W, bias, dest) sets.
// ============================================================
#define LDA 40
#define G_AS (128 * LDA)
#define G_STAGE_B (3 * G_AS * 2)          // Ahi, Alo, W  (30720 B)
#define G_SMEM_B (3 * G_STAGE_B)          // 3 stages (92160 B)

template<bool OUT16>
__global__ __launch_bounds__(256) void gemm_mma_f16x2(
    const __half* __restrict__ Ahi, const __half* __restrict__ Alo,
    const __half* __restrict__ Whb,
    const float* __restrict__ bias0, const float* __restrict__ bias1,
    const float* __restrict__ bias2,
    float* __restrict__ C,
    __half* __restrict__ C0, __half* __restrict__ C1, __half* __restrict__ C2,
    int M, int N, int K, float osc0)
{
    extern __shared__ char smem[];
    const uint32_t sb = smem_u32(smem);

    const int z = blockIdx.z;
    const __half* Bh = Whb + (size_t)z * WN_;
    const float* bias = z == 0 ? bias0 : (z == 1 ? bias1 : bias2);
    __half* Cd = z == 0 ? C0 : (z == 1 ? C1 : C2);
    const float oscale = z == 0 ? osc0 : 1.0f;

    const int t    = threadIdx.x;
    const int lane = t & 31;
    const int wid  = t >> 5;
    const int wm   = (wid & 1) * 64;
    const int wn   = (wid >> 1) * 32;
    const int bm   = blockIdx.y * 128;
    const int bn   = blockIdx.x * 128;

    float acc[4][4][4];
#pragma unroll
    for (int i = 0; i < 4; i++)
#pragma unroll
        for (int j = 0; j < 4; j++)
#pragma unroll
            for (int r = 0; r < 4; r++) acc[i][j][r] = 0.0f;

    const int lr = t >> 2;
    const int lc = (t & 3) * 8;

    const uint32_t aOff = (uint32_t)(((wm + (lane & 15)) * LDA + (lane >> 4) * 8) * 2);
    const uint32_t bOff = (uint32_t)(((wn + (lane >> 4) * 8 + (lane & 7)) * LDA + ((lane >> 3) & 1) * 8) * 2);

#define G_LOAD(s, k0) do {                                                        \
        uint32_t st = sb + (uint32_t)(s) * G_STAGE_B;                             \
        _Pragma("unroll")                                                         \
        for (int bch = 0; bch < 2; bch++) {                                       \
            int r = lr + bch * 64;                                                \
            size_t ga = (size_t)(bm + r) * K + (k0) + lc;                         \
            size_t gb = (size_t)(bn + r) * K + (k0) + lc;                         \
            uint32_t so = (uint32_t)((r * LDA + lc) * 2);                         \
            CP16(st + 0 * G_AS * 2 + so, Ahi + ga);                               \
            CP16(st + 1 * G_AS * 2 + so, Alo + ga);                               \
            CP16(st + 2 * G_AS * 2 + so, Bh + gb);                                \
        }                                                                         \
    } while (0)

    const int NK = K / 32;                 // 32 iterations
    G_LOAD(0, 0);  CP_COMMIT();
    G_LOAD(1, 32); CP_COMMIT();

    int stage = 0;
    for (int it = 0; it < NK; it++) {
        CP_WAIT1();                        // stage it%3 ready (one younger pending)
        __syncthreads();                   // publish to all warps; guards WAR on stage being reloaded

        if (it + 2 < NK) G_LOAD((it + 2) % 3, (it + 2) * 32);
        CP_COMMIT();

        const uint32_t st  = sb + (uint32_t)stage * G_STAGE_B;
        const uint32_t aB  = st;
        const uint32_t alB = st + 1 * G_AS * 2;
        const uint32_t bB  = st + 2 * G_AS * 2;
        stage = stage == 2 ? 0 : stage + 1;

#pragma unroll
        for (int ks = 0; ks < 2; ks++) {
            const uint32_t kb = ks * 32;
            uint32_t bh[8];
#pragma unroll
            for (int pr = 0; pr < 2; pr++) {
                uint32_t ba = bOff + (uint32_t)(pr * 16 * LDA * 2) + kb;
                ldsm_x4(bB + ba, bh[pr*4+0], bh[pr*4+1], bh[pr*4+2], bh[pr*4+3]);
            }
            uint32_t ah[4][4], al[4][4];
#pragma unroll
            for (int mt = 0; mt < 4; mt++) {
                uint32_t aa = aOff + (uint32_t)(mt * 16 * LDA * 2) + kb;
                ldsm_x4(aB + aa,  ah[mt][0], ah[mt][1], ah[mt][2], ah[mt][3]);
                ldsm_x4(alB + aa, al[mt][0], al[mt][1], al[mt][2], al[mt][3]);
            }
#pragma unroll
            for (int mt = 0; mt < 4; mt++) {
#pragma unroll
                for (int nt = 0; nt < 4; nt++) {
                    const int pr = nt >> 1, hf = (nt & 1) * 2;
                    uint32_t b0 = bh[pr*4 + hf], b1 = bh[pr*4 + hf + 1];
                    mma16816(acc[mt][nt], ah[mt][0], ah[mt][1], ah[mt][2], ah[mt][3], b0, b1);
                    mma16816(acc[mt][nt], al[mt][0], al[mt][1], al[mt][2], al[mt][3], b0, b1);
                }
            }
        }
    }

#pragma unroll
    for (int mt = 0; mt < 4; mt++) {
#pragma unroll
        for (int nt = 0; nt < 4; nt++) {
            int row = bm + wm + mt * 16 + (lane >> 2);
            int col = bn + wn + nt * 8 + (lane & 3) * 2;
            float2 bvv = *(const float2*)&bias[col];
            float v0x = (acc[mt][nt][0] + bvv.x) * oscale, v0y = (acc[mt][nt][1] + bvv.y) * oscale;
            float v1x = (acc[mt][nt][2] + bvv.x) * oscale, v1y = (acc[mt][nt][3] + bvv.y) * oscale;
            if (OUT16) {
                *(uint32_t*)&Cd[(size_t)row * N + col]       = pack_h2(v0x, v0y);
                *(uint32_t*)&Cd[(size_t)(row + 8) * N + col] = pack_h2(v1x, v1y);
            } else {
                *(float2*)&C[(size_t)row * N + col] = make_float2(v0x, v0y);
                *(float2*)&C[(size_t)(row + 8) * N + col] = make_float2(v1x, v1y);
            }
        }
    }
}

// ============================================================
// Tensor-core flash ConsMax attention, single fp16,
// 3-stage cp.async pipeline, 1 sync/iter.
// QK^T = 1 MMA, PV = 1 MMA. 128 q-rows/CTA, 8 warps, Bc=64.
// Q pre-scaled by 1/8. Emits C as fp16 hi/lo.
// ============================================================
#define LDV 72
#define A_AS (64 * LDV)
#define A_STAGE_B (2 * A_AS * 2)            // K, V (18432 B)
#define A_MASK_OFF (3 * A_STAGE_B)          // 55296
#define A_SMEM_B (A_MASK_OFF + 3 * 256)     // 56064

__global__ __launch_bounds__(256) void consmax_attn_mma(
    const __half* __restrict__ Q, const __half* __restrict__ K,
    const __half* __restrict__ V,
    const float* __restrict__ mask, const float* __restrict__ gamma,
    __half* __restrict__ Ch, __half* __restrict__ Cl)
{
    extern __shared__ char smem[];
    const uint32_t sb = smem_u32(smem);

    const int qb = blockIdx.x, h = blockIdx.y, b = blockIdx.z;
    const int t = threadIdx.x, lane = t & 31, w = t >> 5;
    const int row0 = b * S_ + qb * 128;

    // ---- Q fragments straight from global (A-frag layout) ----
    uint32_t qf[4][4];
    {
        const int fr = lane >> 2;
        const int fc = (lane & 3) * 2;
        const size_t base = (size_t)(row0 + w * 16 + fr) * HID_ + h * HD_ + fc;
#pragma unroll
        for (int ks = 0; ks < 4; ks++) {
            const size_t g = base + ks * 16;
            qf[ks][0] = *(const uint32_t*)(Q + g);
            qf[ks][1] = *(const uint32_t*)(Q + g + 8 * HID_);
            qf[ks][2] = *(const uint32_t*)(Q + g + 8);
            qf[ks][3] = *(const uint32_t*)(Q + g + 8 * HID_ + 8);
        }
    }

    float m0 = -1e30f, m1 = -1e30f;
    float O[8][4];
#pragma unroll
    for (int nt = 0; nt < 8; nt++)
#pragma unroll
        for (int r = 0; r < 4; r++) O[nt][r] = 0.0f;

#define A_LOAD(s, j0) do {                                                        \
        uint32_t st = sb + (uint32_t)(s) * A_STAGE_B;                             \
        _Pragma("unroll")                                                         \
        for (int i2 = 0; i2 < 2; i2++) {                                          \
            int u = t + 256 * i2;                                                 \
            int r = u >> 3, seg = u & 7;                                          \
            const size_t g = (size_t)(b * S_ + (j0) + r) * HID_ + h * HD_ + seg * 8; \
            uint32_t so = (uint32_t)((r * LDV + seg * 8) * 2);                    \
            CP16(st + 0 * A_AS * 2 + so, K + g);                                  \
            CP16(st + 1 * A_AS * 2 + so, V + g);                                  \
        }                                                                         \
        if (t < 16)                                                               \
            CP16(sb + A_MASK_OFF + (uint32_t)(s) * 256 + t * 16,                  \
                 mask + (size_t)b * S_ + (j0) + t * 4);                           \
    } while (0)

    const int NCH = S_ / 64;               // 32 iterations
    A_LOAD(0, 0);  CP_COMMIT();
    A_LOAD(1, 64); CP_COMMIT();

    int stage = 0;
    for (int it = 0; it < NCH; it++) {
        CP_WAIT1();
        __syncthreads();

        if (it + 2 < NCH) A_LOAD((it + 2) % 3, (it + 2) * 64);
        CP_COMMIT();

        const uint32_t st  = sb + (uint32_t)stage * A_STAGE_B;
        const uint32_t kB  = st;
        const uint32_t vB  = st + 1 * A_AS * 2;
        const float* smask = (const float*)(smem + A_MASK_OFF + stage * 256);
        stage = stage == 2 ? 0 : stage + 1;

        // ---- S = Q K^T (1 MMA per tile) ----
        float sc[8][4];
#pragma unroll
        for (int nt = 0; nt < 8; nt++)
#pragma unroll
            for (int r = 0; r < 4; r++) sc[nt][r] = 0.0f;

#pragma unroll
        for (int ks = 0; ks < 4; ks++) {
            uint32_t bh[4][4];
#pragma unroll
            for (int nb = 0; nb < 4; nb++) {
                uint32_t addr = (uint32_t)(((nb * 16 + (lane >> 4) * 8 + (lane & 7)) * LDV
                                            + ks * 16 + ((lane >> 3) & 1) * 8) * 2);
                ldsm_x4(kB + addr, bh[nb][0], bh[nb][1], bh[nb][2], bh[nb][3]);
            }
#pragma unroll
            for (int nb = 0; nb < 4; nb++) {
                mma16816(sc[2*nb],   qf[ks][0], qf[ks][1], qf[ks][2], qf[ks][3], bh[nb][0], bh[nb][1]);
                mma16816(sc[2*nb+1], qf[ks][0], qf[ks][1], qf[ks][2], qf[ks][3], bh[nb][2], bh[nb][3]);
            }
        }

        // ---- mask + running rowmax ----
        float mn0 = m0, mn1 = m1;
#pragma unroll
        for (int nt = 0; nt < 8; nt++) {
            int col = nt * 8 + (lane & 3) * 2;
            float ma = smask[col], mb2 = smask[col + 1];
            sc[nt][0] += ma; sc[nt][1] += mb2;
            sc[nt][2] += ma; sc[nt][3] += mb2;
            mn0 = fmaxf(mn0, fmaxf(sc[nt][0], sc[nt][1]));
            mn1 = fmaxf(mn1, fmaxf(sc[nt][2], sc[nt][3]));
        }
        mn0 = fmaxf(mn0, __shfl_xor_sync(0xffffffffu, mn0, 1));
        mn0 = fmaxf(mn0, __shfl_xor_sync(0xffffffffu, mn0, 2));
        mn1 = fmaxf(mn1, __shfl_xor_sync(0xffffffffu, mn1, 1));
        mn1 = fmaxf(mn1, __shfl_xor_sync(0xffffffffu, mn1, 2));
        float f0 = __expf(m0 - mn0), f1 = __expf(m1 - mn1);
        m0 = mn0; m1 = mn1;

        // ---- P = exp(s - m) as single fp16 A-frags ----
        uint32_t pa[4][4];
#pragma unroll
        for (int ks = 0; ks < 4; ks++) {
            pa[ks][0] = pack_h2(__expf(sc[2*ks][0] - m0),   __expf(sc[2*ks][1] - m0));
            pa[ks][1] = pack_h2(__expf(sc[2*ks][2] - m1),   __expf(sc[2*ks][3] - m1));
            pa[ks][2] = pack_h2(__expf(sc[2*ks+1][0] - m0), __expf(sc[2*ks+1][1] - m0));
            pa[ks][3] = pack_h2(__expf(sc[2*ks+1][2] - m1), __expf(sc[2*ks+1][3] - m1));
        }

        // ---- rescale O ----
#pragma unroll
        for (int nt = 0; nt < 8; nt++) {
            O[nt][0] *= f0; O[nt][1] *= f0; O[nt][2] *= f1; O[nt][3] *= f1;
        }

        // ---- O += P V (1 MMA per tile) ----
#pragma unroll
        for (int ks = 0; ks < 4; ks++) {
            uint32_t vf[4][4];
#pragma unroll
            for (int db = 0; db < 4; db++) {
                uint32_t addr = (uint32_t)(((ks * 16 + ((lane >> 3) & 1) * 8 + (lane & 7)) * LDV
                                            + db * 16 + (lane >> 4) * 8) * 2);
                ldsm_x4_trans(vB + addr, vf[db][0], vf[db][1], vf[db][2], vf[db][3]);
            }
#pragma unroll
            for (int db = 0; db < 4; db++) {
                mma16816(O[2*db],   pa[ks][0], pa[ks][1], pa[ks][2], pa[ks][3], vf[db][0], vf[db][1]);
                mma16816(O[2*db+1], pa[ks][0], pa[ks][1], pa[ks][2], pa[ks][3], vf[db][2], vf[db][3]);
            }
        }
    }

    // ---- epilogue: O/gamma -> fp16 hi/lo ----
    const float ig = 1.0f / gamma[0];
#pragma unroll
    for (int nt = 0; nt < 8; nt++) {
        int r = row0 + w * 16 + (lane >> 2);
        int col = h * HD_ + nt * 8 + (lane & 3) * 2;
        uint32_t h0, l0, h1, l1;
        pack2_hilo(O[nt][0] * ig, O[nt][1] * ig, h0, l0);
        pack2_hilo(O[nt][2] * ig, O[nt][3] * ig, h1, l1);
        *(uint32_t*)&Ch[(size_t)r * HID_ + col] = h0;
        *(uint32_t*)&Cl[(size_t)r * HID_ + col] = l0;
        *(uint32_t*)&Ch[(size_t)(r + 8) * HID_ + col] = h1;
        *(uint32_t*)&Cl[(size_t)(r + 8) * HID_ + col] = l1;
    }
}

// ============================================================
// Launch
// ============================================================
extern "C" void kernel_launch(void* const* d_in, const int* in_sizes, int n_in,
                              void* d_out, int out_size)
{
    (void)in_sizes; (void)n_in; (void)out_size;
    const float* X    = (const float*)d_in[0];
    const float* mask = (const float*)d_in[1];
    const float* Wq   = (const float*)d_in[2];
    const float* bq   = (const float*)d_in[3];
    const float* Wk   = (const float*)d_in[4];
    const float* bk   = (const float*)d_in[5];
    const float* Wv   = (const float*)d_in[6];
    const float* bv   = (const float*)d_in[7];
    const float* Wo   = (const float*)d_in[8];
    const float* bo   = (const float*)d_in[9];
    const float* gamma = (const float*)d_in[11];   // beta (d_in[10]) cancels exactly
    float* out = (float*)d_out;

    __half *xhi, *xlo, *wh, *qp, *kp, *vp, *chp, *clp;
    cudaGetSymbolAddress((void**)&xhi, g_Xhi);
    cudaGetSymbolAddress((void**)&xlo, g_Xlo);
    cudaGetSymbolAddress((void**)&wh,  g_Wh);
    cudaGetSymbolAddress((void**)&qp,  g_Q);
    cudaGetSymbolAddress((void**)&kp,  g_K);
    cudaGetSymbolAddress((void**)&vp,  g_V);
    cudaGetSymbolAddress((void**)&chp, g_Ch);
    cudaGetSymbolAddress((void**)&clp, g_Cl);

    cudaFuncSetAttribute(gemm_mma_f16x2<true>,  cudaFuncAttributeMaxDynamicSharedMemorySize, G_SMEM_B);
    cudaFuncSetAttribute(gemm_mma_f16x2<false>, cudaFuncAttributeMaxDynamicSharedMemorySize, G_SMEM_B);
    cudaFuncSetAttribute(consmax_attn_mma,      cudaFuncAttributeMaxDynamicSharedMemorySize, A_SMEM_B);

    cvt_split<<<(MTOT * HID_ / 4 + 255) / 256, 256>>>(X, xhi, xlo, MTOT * HID_ / 4);
    cvt_h4<<<(4 * WN_ / 4) / 256, 256>>>(Wq, Wk, Wv, Wo, wh);

    // fused QKV projection (2-term): z = 0(Q, x1/8), 1(K), 2(V) — single fp16 outputs
    dim3 gq(HID_ / 128, MTOT / 128, 3);
    gemm_mma_f16x2<true><<<gq, 256, G_SMEM_B>>>(xhi, xlo, wh,
                                                bq, bk, bv, nullptr,
                                                qp, kp, vp,
                                                MTOT, HID_, HID_, 0.125f);

    dim3 ga(S_ / 128, NH_, B_);        // (16, 16, 2)
    consmax_attn_mma<<<ga, 256, A_SMEM_B>>>(qp, kp, vp, mask, gamma, chp, clp);

    // output projection (2-term C hi/lo) -> fp32 out
    dim3 go(HID_ / 128, MTOT / 128, 1);
    gemm_mma_f16x2<false><<<go, 256, G_SMEM_B>>>(chp, clp, wh + 3 * (size_t)WN_,
                                                 bo, nullptr, nullptr,
                                                 out, nullptr, nullptr, nullptr,
                                                 MTOT, HID_, HID_, 1.0f);
}

// round 12
// speedup vs baseline: 1.3541x; 1.0472x over previous
#include <cuda_runtime.h>
#include <cuda_fp16.h>
#include <math.h>
#include <stdint.h>

#define B_    2
#define S_    2048
#define HID_  1024
#define NH_   16
#define HD_   64
#define MTOT  (B_ * S_)
#define WN_   (HID_ * HID_)
#define LOG2E 1.4426950408889634f

// ---------------- scratch (static device allocations) ----------------
__device__ __half g_Xhi[MTOT * HID_];
__device__ __half g_Xlo[MTOT * HID_];
__device__ __half g_Wh[4 * WN_];
__device__ __half g_Q[MTOT * HID_];
__device__ __half g_K[MTOT * HID_];
__device__ __half g_V[MTOT * HID_];
__device__ __half g_Ch[MTOT * HID_];
__device__ __half g_Cl[MTOT * HID_];
__device__ float  g_Madd[MTOT];

// ---------------- helpers (baseline PTX only) ----------------
__device__ __forceinline__ uint32_t smem_u32(const void* p) {
    uint32_t a;
    asm("{ .reg .u64 t; cvta.to.shared.u64 t, %1; cvt.u32.u64 %0, t; }" : "=r"(a) : "l"(p));
    return a;
}
__device__ __forceinline__ void ldsm_x4(uint32_t addr, uint32_t& r0, uint32_t& r1,
                                        uint32_t& r2, uint32_t& r3) {
    asm volatile("ldmatrix.sync.aligned.m8n8.x4.shared.b16 {%0,%1,%2,%3}, [%4];"
                 : "=r"(r0), "=r"(r1), "=r"(r2), "=r"(r3) : "r"(addr));
}
__device__ __forceinline__ void ldsm_x4_trans(uint32_t addr, uint32_t& r0, uint32_t& r1,
                                              uint32_t& r2, uint32_t& r3) {
    asm volatile("ldmatrix.sync.aligned.m8n8.x4.trans.shared.b16 {%0,%1,%2,%3}, [%4];"
                 : "=r"(r0), "=r"(r1), "=r"(r2), "=r"(r3) : "r"(addr));
}
__device__ __forceinline__ void mma16816(float* c, uint32_t a0, uint32_t a1,
                                         uint32_t a2, uint32_t a3,
                                         uint32_t b0, uint32_t b1) {
    asm volatile(
        "mma.sync.aligned.m16n8k16.row.col.f32.f16.f16.f32 "
        "{%0,%1,%2,%3}, {%4,%5,%6,%7}, {%8,%9}, {%0,%1,%2,%3};"
        : "+f"(c[0]), "+f"(c[1]), "+f"(c[2]), "+f"(c[3])
        : "r"(a0), "r"(a1), "r"(a2), "r"(a3), "r"(b0), "r"(b1));
}
__device__ __forceinline__ uint32_t pack_h2(float a, float b) {
    __half2 h = __floats2half2_rn(a, b);
    return *(uint32_t*)&h;
}
__device__ __forceinline__ void pack2_hilo(float a, float b, uint32_t& hi, uint32_t& lo) {
    __half2 h = __floats2half2_rn(a, b);
    float2 hf = __half22float2(h);
    __half2 l = __floats2half2_rn(a - hf.x, b - hf.y);
    hi = *(uint32_t*)&h;
    lo = *(uint32_t*)&l;
}
__device__ __forceinline__ float ex2(float x) {
    float y;
    asm("ex2.approx.ftz.f32 %0, %1;" : "=f"(y) : "f"(x));
    return y;
}
#define CP16(dst, src) \
    asm volatile("cp.async.cg.shared.global [%0], [%1], 16;" :: "r"(dst), "l"(src))
#define CP_COMMIT() asm volatile("cp.async.commit_group;")
#define CP_WAIT1()  asm volatile("cp.async.wait_group 1;")

// ---------------- converters ----------------
__global__ __launch_bounds__(256) void cvt_split(
    const float* __restrict__ in, __half* __restrict__ hi,
    __half* __restrict__ lo, int n4)
{
    int i = blockIdx.x * blockDim.x + threadIdx.x;
    if (i >= n4) return;
    float4 v = ((const float4*)in)[i];
    uint32_t h0, l0, h1, l1;
    pack2_hilo(v.x, v.y, h0, l0);
    pack2_hilo(v.z, v.w, h1, l1);
    ((uint2*)hi)[i] = make_uint2(h0, h1);
    ((uint2*)lo)[i] = make_uint2(l0, l1);
}

__global__ __launch_bounds__(256) void cvt_h4(
    const float* __restrict__ w0, const float* __restrict__ w1,
    const float* __restrict__ w2, const float* __restrict__ w3,
    __half* __restrict__ wh)
{
    const int n4per = WN_ / 4;
    int i = blockIdx.x * blockDim.x + threadIdx.x;
    int sel = i / n4per;
    int j   = i - sel * n4per;
    const float* src = sel == 0 ? w0 : (sel == 1 ? w1 : (sel == 2 ? w2 : w3));
    float4 v = ((const float4*)src)[j];
    ((uint2*)wh)[i] = make_uint2(pack_h2(v.x, v.y), pack_h2(v.z, v.w));
}

// mask -> additive log2-domain term: (1-mask)*(-10000)*log2e
__global__ __launch_bounds__(256) void msk_prep(
    const float* __restrict__ mask, float* __restrict__ madd, int n)
{
    int i = blockIdx.x * blockDim.x + threadIdx.x;
    if (i >= n) return;
    madd[i] = (1.0f - mask[i]) * (-10000.0f * LOG2E);
}

// ============================================================
// Tensor-core GEMM, 3-stage cp.async, deferred-wait pipeline.
// fp16 2-term: C = ((Ahi+Alo) @ W^T + bias) * oscale.
// grid.z selects among up to 3 (W, bias, dest) sets.
// ============================================================
#define LDA 40
#define G_AS (128 * LDA)
#define G_STAGE_B (3 * G_AS * 2)          // Ahi, Alo, W  (30720 B)
#define G_SMEM_B (3 * G_STAGE_B)          // 3 stages (92160 B)

template<bool OUT16>
__global__ __launch_bounds__(256) void gemm_mma_f16x2(
    const __half* __restrict__ Ahi, const __half* __restrict__ Alo,
    const __half* __restrict__ Whb,
    const float* __restrict__ bias0, const float* __restrict__ bias1,
    const float* __restrict__ bias2,
    float* __restrict__ C,
    __half* __restrict__ C0, __half* __restrict__ C1, __half* __restrict__ C2,
    int M, int N, int K, float osc0)
{
    extern __shared__ char smem[];
    const uint32_t sb = smem_u32(smem);

    const int z = blockIdx.z;
    const __half* Bh = Whb + (size_t)z * WN_;
    const float* bias = z == 0 ? bias0 : (z == 1 ? bias1 : bias2);
    __half* Cd = z == 0 ? C0 : (z == 1 ? C1 : C2);
    const float oscale = z == 0 ? osc0 : 1.0f;

    const int t    = threadIdx.x;
    const int lane = t & 31;
    const int wid  = t >> 5;
    const int wm   = (wid & 1) * 64;
    const int wn   = (wid >> 1) * 32;
    const int bm   = blockIdx.y * 128;
    const int bn   = blockIdx.x * 128;

    float acc[4][4][4];
#pragma unroll
    for (int i = 0; i < 4; i++)
#pragma unroll
        for (int j = 0; j < 4; j++)
#pragma unroll
            for (int r = 0; r < 4; r++) acc[i][j][r] = 0.0f;

    const int lr = t >> 2;
    const int lc = (t & 3) * 8;

    const uint32_t aOff = (uint32_t)(((wm + (lane & 15)) * LDA + (lane >> 4) * 8) * 2);
    const uint32_t bOff = (uint32_t)(((wn + (lane >> 4) * 8 + (lane & 7)) * LDA + ((lane >> 3) & 1) * 8) * 2);

#define G_LOAD(s, k0) do {                                                        \
        uint32_t st = sb + (uint32_t)(s) * G_STAGE_B;                             \
        _Pragma("unroll")                                                         \
        for (int bch = 0; bch < 2; bch++) {                                       \
            int r = lr + bch * 64;                                                \
            size_t ga = (size_t)(bm + r) * K + (k0) + lc;                         \
            size_t gb = (size_t)(bn + r) * K + (k0) + lc;                         \
            uint32_t so = (uint32_t)((r * LDA + lc) * 2);                         \
            CP16(st + 0 * G_AS * 2 + so, Ahi + ga);                               \
            CP16(st + 1 * G_AS * 2 + so, Alo + ga);                               \
            CP16(st + 2 * G_AS * 2 + so, Bh + gb);                                \
        }                                                                         \
    } while (0)

    const int NK = K / 32;                 // 32 iterations
    G_LOAD(0, 0);  CP_COMMIT();
    G_LOAD(1, 32); CP_COMMIT();
    CP_WAIT1();                            // stage 0 ready

    int stage = 0;
    for (int it = 0; it < NK; it++) {
        __syncthreads();                   // all warps done consuming stage (it-1) == (it+2)%3

        if (it + 2 < NK) { G_LOAD((it + 2) % 3, (it + 2) * 32); CP_COMMIT(); }

        const uint32_t st  = sb + (uint32_t)stage * G_STAGE_B;
        const uint32_t aB  = st;
        const uint32_t alB = st + 1 * G_AS * 2;
        const uint32_t bB  = st + 2 * G_AS * 2;
        stage = stage == 2 ? 0 : stage + 1;

#pragma unroll
        for (int ks = 0; ks < 2; ks++) {
            const uint32_t kb = ks * 32;
            uint32_t bh[8];
#pragma unroll
            for (int pr = 0; pr < 2; pr++) {
                uint32_t ba = bOff + (uint32_t)(pr * 16 * LDA * 2) + kb;
                ldsm_x4(bB + ba, bh[pr*4+0], bh[pr*4+1], bh[pr*4+2], bh[pr*4+3]);
            }
            uint32_t ah[4][4], al[4][4];
#pragma unroll
            for (int mt = 0; mt < 4; mt++) {
                uint32_t aa = aOff + (uint32_t)(mt * 16 * LDA * 2) + kb;
                ldsm_x4(aB + aa,  ah[mt][0], ah[mt][1], ah[mt][2], ah[mt][3]);
                ldsm_x4(alB + aa, al[mt][0], al[mt][1], al[mt][2], al[mt][3]);
            }
#pragma unroll
            for (int mt = 0; mt < 4; mt++) {
#pragma unroll
                for (int nt = 0; nt < 4; nt++) {
                    const int pr = nt >> 1, hf = (nt & 1) * 2;
                    uint32_t b0 = bh[pr*4 + hf], b1 = bh[pr*4 + hf + 1];
                    mma16816(acc[mt][nt], ah[mt][0], ah[mt][1], ah[mt][2], ah[mt][3], b0, b1);
                    mma16816(acc[mt][nt], al[mt][0], al[mt][1], al[mt][2], al[mt][3], b0, b1);
                }
            }
        }
        CP_WAIT1();                        // next stage ready; hidden behind the MMAs above
    }

#pragma unroll
    for (int mt = 0; mt < 4; mt++) {
#pragma unroll
        for (int nt = 0; nt < 4; nt++) {
            int row = bm + wm + mt * 16 + (lane >> 2);
            int col = bn + wn + nt * 8 + (lane & 3) * 2;
            float2 bvv = *(const float2*)&bias[col];
            float v0x = (acc[mt][nt][0] + bvv.x) * oscale, v0y = (acc[mt][nt][1] + bvv.y) * oscale;
            float v1x = (acc[mt][nt][2] + bvv.x) * oscale, v1y = (acc[mt][nt][3] + bvv.y) * oscale;
            if (OUT16) {
                *(uint32_t*)&Cd[(size_t)row * N + col]       = pack_h2(v0x, v0y);
                *(uint32_t*)&Cd[(size_t)(row + 8) * N + col] = pack_h2(v1x, v1y);
            } else {
                *(float2*)&C[(size_t)row * N + col] = make_float2(v0x, v0y);
                *(float2*)&C[(size_t)(row + 8) * N + col] = make_float2(v1x, v1y);
            }
        }
    }
}

// ============================================================
// Tensor-core flash ConsMax attention, single fp16, exp2 domain,
// 3-stage cp.async, deferred-wait pipeline.
// QK^T = 1 MMA, PV = 1 MMA. 128 q-rows/CTA, 8 warps, Bc=64.
// Q pre-scaled by log2e/8 upstream; mask pre-scaled by log2e.
// ============================================================
#define LDV 72
#define A_AS (64 * LDV)
#define A_STAGE_B (2 * A_AS * 2)            // K, V (18432 B)
#define A_MASK_OFF (3 * A_STAGE_B)          // 55296
#define A_SMEM_B (A_MASK_OFF + 3 * 256)     // 56064

__global__ __launch_bounds__(256) void consmax_attn_mma(
    const __half* __restrict__ Q, const __half* __restrict__ K,
    const __half* __restrict__ V,
    const float* __restrict__ madd, const float* __restrict__ gamma,
    __half* __restrict__ Ch, __half* __restrict__ Cl)
{
    extern __shared__ char smem[];
    const uint32_t sb = smem_u32(smem);

    const int qb = blockIdx.x, h = blockIdx.y, b = blockIdx.z;
    const int t = threadIdx.x, lane = t & 31, w = t >> 5;
    const int row0 = b * S_ + qb * 128;

    // ---- Q fragments straight from global (A-frag layout) ----
    uint32_t qf[4][4];
    {
        const int fr = lane >> 2;
        const int fc = (lane & 3) * 2;
        const size_t base = (size_t)(row0 + w * 16 + fr) * HID_ + h * HD_ + fc;
#pragma unroll
        for (int ks = 0; ks < 4; ks++) {
            const size_t g = base + ks * 16;
            qf[ks][0] = *(const uint32_t*)(Q + g);
            qf[ks][1] = *(const uint32_t*)(Q + g + 8 * HID_);
            qf[ks][2] = *(const uint32_t*)(Q + g + 8);
            qf[ks][3] = *(const uint32_t*)(Q + g + 8 * HID_ + 8);
        }
    }

    float m0 = -1e30f, m1 = -1e30f;
    float O[8][4];
#pragma unroll
    for (int nt = 0; nt < 8; nt++)
#pragma unroll
        for (int r = 0; r < 4; r++) O[nt][r] = 0.0f;

#define A_LOAD(s, j0) do {                                                        \
        uint32_t st = sb + (uint32_t)(s) * A_STAGE_B;                             \
        _Pragma("unroll")                                                         \
        for (int i2 = 0; i2 < 2; i2++) {                                          \
            int u = t + 256 * i2;                                                 \
            int r = u >> 3, seg = u & 7;                                          \
            const size_t g = (size_t)(b * S_ + (j0) + r) * HID_ + h * HD_ + seg * 8; \
            uint32_t so = (uint32_t)((r * LDV + seg * 8) * 2);                    \
            CP16(st + 0 * A_AS * 2 + so, K + g);                                  \
            CP16(st + 1 * A_AS * 2 + so, V + g);                                  \
        }                                                                         \
        if (t < 16)                                                               \
            CP16(sb + A_MASK_OFF + (uint32_t)(s) * 256 + t * 16,                  \
                 madd + (size_t)b * S_ + (j0) + t * 4);                           \
    } while (0)

    const int NCH = S_ / 64;               // 32 iterations
    A_LOAD(0, 0);  CP_COMMIT();
    A_LOAD(1, 64); CP_COMMIT();
    CP_WAIT1();                            // stage 0 ready

    int stage = 0;
    for (int it = 0; it < NCH; it++) {
        __syncthreads();

        if (it + 2 < NCH) { A_LOAD((it + 2) % 3, (it + 2) * 64); CP_COMMIT(); }

        const uint32_t st  = sb + (uint32_t)stage * A_STAGE_B;
        const uint32_t kB  = st;
        const uint32_t vB  = st + 1 * A_AS * 2;
        const float* smask = (const float*)(smem + A_MASK_OFF + stage * 256);
        stage = stage == 2 ? 0 : stage + 1;

        // ---- S2 = log2e*(Q K^T)/8 (scale folded into Q), 1 MMA/tile ----
        float sc[8][4];
#pragma unroll
        for (int nt = 0; nt < 8; nt++)
#pragma unroll
            for (int r = 0; r < 4; r++) sc[nt][r] = 0.0f;

#pragma unroll
        for (int ks = 0; ks < 4; ks++) {
            uint32_t bh[4][4];
#pragma unroll
            for (int nb = 0; nb < 4; nb++) {
                uint32_t addr = (uint32_t)(((nb * 16 + (lane >> 4) * 8 + (lane & 7)) * LDV
                                            + ks * 16 + ((lane >> 3) & 1) * 8) * 2);
                ldsm_x4(kB + addr, bh[nb][0], bh[nb][1], bh[nb][2], bh[nb][3]);
            }
#pragma unroll
            for (int nb = 0; nb < 4; nb++) {
                mma16816(sc[2*nb],   qf[ks][0], qf[ks][1], qf[ks][2], qf[ks][3], bh[nb][0], bh[nb][1]);
                mma16816(sc[2*nb+1], qf[ks][0], qf[ks][1], qf[ks][2], qf[ks][3], bh[nb][2], bh[nb][3]);
            }
        }

        // ---- mask + running rowmax (log2 domain) ----
        float mn0 = m0, mn1 = m1;
#pragma unroll
        for (int nt = 0; nt < 8; nt++) {
            int col = nt * 8 + (lane & 3) * 2;
            float ma = smask[col], mb2 = smask[col + 1];
            sc[nt][0] += ma; sc[nt][1] += mb2;
            sc[nt][2] += ma; sc[nt][3] += mb2;
            mn0 = fmaxf(mn0, fmaxf(sc[nt][0], sc[nt][1]));
            mn1 = fmaxf(mn1, fmaxf(sc[nt][2], sc[nt][3]));
        }
        mn0 = fmaxf(mn0, __shfl_xor_sync(0xffffffffu, mn0, 1));
        mn0 = fmaxf(mn0, __shfl_xor_sync(0xffffffffu, mn0, 2));
        mn1 = fmaxf(mn1, __shfl_xor_sync(0xffffffffu, mn1, 1));
        mn1 = fmaxf(mn1, __shfl_xor_sync(0xffffffffu, mn1, 2));
        float f0 = ex2(m0 - mn0), f1 = ex2(m1 - mn1);
        m0 = mn0; m1 = mn1;

        // ---- P = exp2(s2 - m2) as single fp16 A-frags ----
        uint32_t pa[4][4];
#pragma unroll
        for (int ks = 0; ks < 4; ks++) {
            pa[ks][0] = pack_h2(ex2(sc[2*ks][0] - m0),   ex2(sc[2*ks][1] - m0));
            pa[ks][1] = pack_h2(ex2(sc[2*ks][2] - m1),   ex2(sc[2*ks][3] - m1));
            pa[ks][2] = pack_h2(ex2(sc[2*ks+1][0] - m0), ex2(sc[2*ks+1][1] - m0));
            pa[ks][3] = pack_h2(ex2(sc[2*ks+1][2] - m1), ex2(sc[2*ks+1][3] - m1));
        }

        // ---- rescale O ----
#pragma unroll
        for (int nt = 0; nt < 8; nt++) {
            O[nt][0] *= f0; O[nt][1] *= f0; O[nt][2] *= f1; O[nt][3] *= f1;
        }

        // ---- O += P V (1 MMA per tile) ----
#pragma unroll
        for (int ks = 0; ks < 4; ks++) {
            uint32_t vf[4][4];
#pragma unroll
            for (int db = 0; db < 4; db++) {
                uint32_t addr = (uint32_t)(((ks * 16 + ((lane >> 3) & 1) * 8 + (lane & 7)) * LDV
                                            + db * 16 + (lane >> 4) * 8) * 2);
                ldsm_x4_trans(vB + addr, vf[db][0], vf[db][1], vf[db][2], vf[db][3]);
            }
#pragma unroll
            for (int db = 0; db < 4; db++) {
                mma16816(O[2*db],   pa[ks][0], pa[ks][1], pa[ks][2], pa[ks][3], vf[db][0], vf[db][1]);
                mma16816(O[2*db+1], pa[ks][0], pa[ks][1], pa[ks][2], pa[ks][3], vf[db][2], vf[db][3]);
            }
        }
        CP_WAIT1();                        // next stage ready; hidden behind this chunk's work
    }

    // ---- epilogue: O/gamma -> fp16 hi/lo ----
    const float ig = 1.0f / gamma[0];
#pragma unroll
    for (int nt = 0; nt < 8; nt++) {
        int r = row0 + w * 16 + (lane >> 2);
        int col = h * HD_ + nt * 8 + (lane & 3) * 2;
        uint32_t h0, l0, h1, l1;
        pack2_hilo(O[nt][0] * ig, O[nt][1] * ig, h0, l0);
        pack2_hilo(O[nt][2] * ig, O[nt][3] * ig, h1, l1);
        *(uint32_t*)&Ch[(size_t)r * HID_ + col] = h0;
        *(uint32_t*)&Cl[(size_t)r * HID_ + col] = l0;
        *(uint32_t*)&Ch[(size_t)(r + 8) * HID_ + col] = h1;
        *(uint32_t*)&Cl[(size_t)(r + 8) * HID_ + col] = l1;
    }
}

// ============================================================
// Launch
// ============================================================
extern "C" void kernel_launch(void* const* d_in, const int* in_sizes, int n_in,
                              void* d_out, int out_size)
{
    (void)in_sizes; (void)n_in; (void)out_size;
    const float* X    = (const float*)d_in[0];
    const float* mask = (const float*)d_in[1];
    const float* Wq   = (const float*)d_in[2];
    const float* bq   = (const float*)d_in[3];
    const float* Wk   = (const float*)d_in[4];
    const float* bk   = (const float*)d_in[5];
    const float* Wv   = (const float*)d_in[6];
    const float* bv   = (const float*)d_in[7];
    const float* Wo   = (const float*)d_in[8];
    const float* bo   = (const float*)d_in[9];
    const float* gamma = (const float*)d_in[11];   // beta (d_in[10]) cancels exactly
    float* out = (float*)d_out;

    __half *xhi, *xlo, *wh, *qp, *kp, *vp, *chp, *clp;
    float* mad;
    cudaGetSymbolAddress((void**)&xhi, g_Xhi);
    cudaGetSymbolAddress((void**)&xlo, g_Xlo);
    cudaGetSymbolAddress((void**)&wh,  g_Wh);
    cudaGetSymbolAddress((void**)&qp,  g_Q);
    cudaGetSymbolAddress((void**)&kp,  g_K);
    cudaGetSymbolAddress((void**)&vp,  g_V);
    cudaGetSymbolAddress((void**)&chp, g_Ch);
    cudaGetSymbolAddress((void**)&clp, g_Cl);
    cudaGetSymbolAddress((void**)&mad, g_Madd);

    cudaFuncSetAttribute(gemm_mma_f16x2<true>,  cudaFuncAttributeMaxDynamicSharedMemorySize, G_SMEM_B);
    cudaFuncSetAttribute(gemm_mma_f16x2<false>, cudaFuncAttributeMaxDynamicSharedMemorySize, G_SMEM_B);
    cudaFuncSetAttribute(consmax_attn_mma,      cudaFuncAttributeMaxDynamicSharedMemorySize, A_SMEM_B);

    cvt_split<<<(MTOT * HID_ / 4 + 255) / 256, 256>>>(X, xhi, xlo, MTOT * HID_ / 4);
    cvt_h4<<<(4 * WN_ / 4) / 256, 256>>>(Wq, Wk, Wv, Wo, wh);
    msk_prep<<<(MTOT + 255) / 256, 256>>>(mask, mad, MTOT);

    // fused QKV projection (2-term): z = 0(Q, x log2e/8), 1(K), 2(V)
    dim3 gq(HID_ / 128, MTOT / 128, 3);
    gemm_mma_f16x2<true><<<gq, 256, G_SMEM_B>>>(xhi, xlo, wh,
                                                bq, bk, bv, nullptr,
                                                qp, kp, vp,
                                                MTOT, HID_, HID_, 0.125f * LOG2E);

    dim3 ga(S_ / 128, NH_, B_);        // (16, 16, 2)
    consmax_attn_mma<<<ga, 256, A_SMEM_B>>>(qp, kp, vp, mad, gamma, chp, clp);

    // output projection (2-term C hi/lo) -> fp32 out
    dim3 go(HID_ / 128, MTOT / 128, 1);
    gemm_mma_f16x2<false><<<go, 256, G_SMEM_B>>>(chp, clp, wh + 3 * (size_t)WN_,
                                                 bo, nullptr, nullptr,
                                                 out, nullptr, nullptr, nullptr,
                                                 MTOT, HID_, HID_, 1.0f);
}

// round 13
// speedup vs baseline: 1.7131x; 1.2651x over previous
#include <cuda_runtime.h>
#include <cuda_fp16.h>
#include <math.h>
#include <stdint.h>

#define B_    2
#define S_    2048
#define HID_  1024
#define NH_   16
#define HD_   64
#define MTOT  (B_ * S_)
#define WN_   (HID_ * HID_)
#define LOG2E 1.4426950408889634f

// ---------------- scratch (static device allocations) ----------------
__device__ __half g_Xh[MTOT * HID_];
__device__ __half g_Wh[4 * WN_];
__device__ __half g_Q[MTOT * HID_];
__device__ __half g_K[MTOT * HID_];
__device__ __half g_V[MTOT * HID_];
__device__ __half g_C[MTOT * HID_];
__device__ float  g_Madd[MTOT];

// ---------------- helpers (baseline PTX only) ----------------
__device__ __forceinline__ uint32_t smem_u32(const void* p) {
    uint32_t a;
    asm("{ .reg .u64 t; cvta.to.shared.u64 t, %1; cvt.u32.u64 %0, t; }" : "=r"(a) : "l"(p));
    return a;
}
__device__ __forceinline__ void ldsm_x4(uint32_t addr, uint32_t& r0, uint32_t& r1,
                                        uint32_t& r2, uint32_t& r3) {
    asm volatile("ldmatrix.sync.aligned.m8n8.x4.shared.b16 {%0,%1,%2,%3}, [%4];"
                 : "=r"(r0), "=r"(r1), "=r"(r2), "=r"(r3) : "r"(addr));
}
__device__ __forceinline__ void ldsm_x4_trans(uint32_t addr, uint32_t& r0, uint32_t& r1,
                                              uint32_t& r2, uint32_t& r3) {
    asm volatile("ldmatrix.sync.aligned.m8n8.x4.trans.shared.b16 {%0,%1,%2,%3}, [%4];"
                 : "=r"(r0), "=r"(r1), "=r"(r2), "=r"(r3) : "r"(addr));
}
__device__ __forceinline__ void mma16816(float* c, uint32_t a0, uint32_t a1,
                                         uint32_t a2, uint32_t a3,
                                         uint32_t b0, uint32_t b1) {
    asm volatile(
        "mma.sync.aligned.m16n8k16.row.col.f32.f16.f16.f32 "
        "{%0,%1,%2,%3}, {%4,%5,%6,%7}, {%8,%9}, {%0,%1,%2,%3};"
        : "+f"(c[0]), "+f"(c[1]), "+f"(c[2]), "+f"(c[3])
        : "r"(a0), "r"(a1), "r"(a2), "r"(a3), "r"(b0), "r"(b1));
}
__device__ __forceinline__ uint32_t pack_h2(float a, float b) {
    __half2 h = __floats2half2_rn(a, b);
    return *(uint32_t*)&h;
}
__device__ __forceinline__ float ex2(float x) {
    float y;
    asm("ex2.approx.ftz.f32 %0, %1;" : "=f"(y) : "f"(x));
    return y;
}
#define CP16(dst, src) \
    asm volatile("cp.async.cg.shared.global [%0], [%1], 16;" :: "r"(dst), "l"(src))
#define CP_COMMIT() asm volatile("cp.async.commit_group;")
#define CP_WAIT1()  asm volatile("cp.async.wait_group 1;")

// ---------------- converters ----------------
__global__ __launch_bounds__(256) void cvt_h(
    const float* __restrict__ in, __half* __restrict__ outp, int n4)
{
    int i = blockIdx.x * blockDim.x + threadIdx.x;
    if (i >= n4) return;
    float4 v = ((const float4*)in)[i];
    ((uint2*)outp)[i] = make_uint2(pack_h2(v.x, v.y), pack_h2(v.z, v.w));
}

__global__ __launch_bounds__(256) void cvt_h4(
    const float* __restrict__ w0, const float* __restrict__ w1,
    const float* __restrict__ w2, const float* __restrict__ w3,
    __half* __restrict__ wh)
{
    const int n4per = WN_ / 4;
    int i = blockIdx.x * blockDim.x + threadIdx.x;
    int sel = i / n4per;
    int j   = i - sel * n4per;
    const float* src = sel == 0 ? w0 : (sel == 1 ? w1 : (sel == 2 ? w2 : w3));
    float4 v = ((const float4*)src)[j];
    ((uint2*)wh)[i] = make_uint2(pack_h2(v.x, v.y), pack_h2(v.z, v.w));
}

// mask -> additive log2-domain term: (1-mask)*(-10000)*log2e
__global__ __launch_bounds__(256) void msk_prep(
    const float* __restrict__ mask, float* __restrict__ madd, int n)
{
    int i = blockIdx.x * blockDim.x + threadIdx.x;
    if (i >= n) return;
    madd[i] = (1.0f - mask[i]) * (-10000.0f * LOG2E);
}

// ============================================================
// Tensor-core GEMM, 3-stage cp.async, deferred-wait pipeline.
// Single fp16 A and W: C = (A @ W^T + bias) * oscale.
// grid.z selects among up to 3 (W, bias, dest) sets.
// ============================================================
#define LDA 40
#define G_AS (128 * LDA)
#define G_STAGE_B (2 * G_AS * 2)          // A, W  (20480 B)
#define G_SMEM_B (3 * G_STAGE_B)          // 3 stages (61440 B)

template<bool OUT16>
__global__ __launch_bounds__(256) void gemm_mma_f16(
    const __half* __restrict__ A,
    const __half* __restrict__ Whb,
    const float* __restrict__ bias0, const float* __restrict__ bias1,
    const float* __restrict__ bias2,
    float* __restrict__ C,
    __half* __restrict__ C0, __half* __restrict__ C1, __half* __restrict__ C2,
    int M, int N, int K, float osc0)
{
    extern __shared__ char smem[];
    const uint32_t sb = smem_u32(smem);

    const int z = blockIdx.z;
    const __half* Bh = Whb + (size_t)z * WN_;
    const float* bias = z == 0 ? bias0 : (z == 1 ? bias1 : bias2);
    __half* Cd = z == 0 ? C0 : (z == 1 ? C1 : C2);
    const float oscale = z == 0 ? osc0 : 1.0f;

    const int t    = threadIdx.x;
    const int lane = t & 31;
    const int wid  = t >> 5;
    const int wm   = (wid & 1) * 64;
    const int wn   = (wid >> 1) * 32;
    const int bm   = blockIdx.y * 128;
    const int bn   = blockIdx.x * 128;

    float acc[4][4][4];
#pragma unroll
    for (int i = 0; i < 4; i++)
#pragma unroll
        for (int j = 0; j < 4; j++)
#pragma unroll
            for (int r = 0; r < 4; r++) acc[i][j][r] = 0.0f;

    const int lr = t >> 2;
    const int lc = (t & 3) * 8;

    const uint32_t aOff = (uint32_t)(((wm + (lane & 15)) * LDA + (lane >> 4) * 8) * 2);
    const uint32_t bOff = (uint32_t)(((wn + (lane >> 4) * 8 + (lane & 7)) * LDA + ((lane >> 3) & 1) * 8) * 2);

#define G_LOAD(s, k0) do {                                                        \
        uint32_t st = sb + (uint32_t)(s) * G_STAGE_B;                             \
        _Pragma("unroll")                                                         \
        for (int bch = 0; bch < 2; bch++) {                                       \
            int r = lr + bch * 64;                                                \
            size_t ga = (size_t)(bm + r) * K + (k0) + lc;                         \
            size_t gb = (size_t)(bn + r) * K + (k0) + lc;                         \
            uint32_t so = (uint32_t)((r * LDA + lc) * 2);                         \
            CP16(st + 0 * G_AS * 2 + so, A + ga);                                 \
            CP16(st + 1 * G_AS * 2 + so, Bh + gb);                                \
        }                                                                         \
    } while (0)

    const int NK = K / 32;                 // 32 iterations
    G_LOAD(0, 0);  CP_COMMIT();
    G_LOAD(1, 32); CP_COMMIT();
    CP_WAIT1();                            // stage 0 ready

    int stage = 0;
    for (int it = 0; it < NK; it++) {
        __syncthreads();                   // all warps done consuming stage (it-1) == (it+2)%3

        if (it + 2 < NK) { G_LOAD((it + 2) % 3, (it + 2) * 32); CP_COMMIT(); }

        const uint32_t st = sb + (uint32_t)stage * G_STAGE_B;
        const uint32_t aB = st;
        const uint32_t bB = st + 1 * G_AS * 2;
        stage = stage == 2 ? 0 : stage + 1;

#pragma unroll
        for (int ks = 0; ks < 2; ks++) {
            const uint32_t kb = ks * 32;
            uint32_t bh[8];
#pragma unroll
            for (int pr = 0; pr < 2; pr++) {
                uint32_t ba = bOff + (uint32_t)(pr * 16 * LDA * 2) + kb;
                ldsm_x4(bB + ba, bh[pr*4+0], bh[pr*4+1], bh[pr*4+2], bh[pr*4+3]);
            }
            uint32_t ah[4][4];
#pragma unroll
            for (int mt = 0; mt < 4; mt++) {
                uint32_t aa = aOff + (uint32_t)(mt * 16 * LDA * 2) + kb;
                ldsm_x4(aB + aa, ah[mt][0], ah[mt][1], ah[mt][2], ah[mt][3]);
            }
#pragma unroll
            for (int mt = 0; mt < 4; mt++) {
#pragma unroll
                for (int nt = 0; nt < 4; nt++) {
                    const int pr = nt >> 1, hf = (nt & 1) * 2;
                    mma16816(acc[mt][nt], ah[mt][0], ah[mt][1], ah[mt][2], ah[mt][3],
                             bh[pr*4 + hf], bh[pr*4 + hf + 1]);
                }
            }
        }
        CP_WAIT1();                        // next stage ready; hidden behind the MMAs above
    }

#pragma unroll
    for (int mt = 0; mt < 4; mt++) {
#pragma unroll
        for (int nt = 0; nt < 4; nt++) {
            int row = bm + wm + mt * 16 + (lane >> 2);
            int col = bn + wn + nt * 8 + (lane & 3) * 2;
            float2 bvv = *(const float2*)&bias[col];
            float v0x = (acc[mt][nt][0] + bvv.x) * oscale, v0y = (acc[mt][nt][1] + bvv.y) * oscale;
            float v1x = (acc[mt][nt][2] + bvv.x) * oscale, v1y = (acc[mt][nt][3] + bvv.y) * oscale;
            if (OUT16) {
                *(uint32_t*)&Cd[(size_t)row * N + col]       = pack_h2(v0x, v0y);
                *(uint32_t*)&Cd[(size_t)(row + 8) * N + col] = pack_h2(v1x, v1y);
            } else {
                *(float2*)&C[(size_t)row * N + col] = make_float2(v0x, v0y);
                *(float2*)&C[(size_t)(row + 8) * N + col] = make_float2(v1x, v1y);
            }
        }
    }
}

// ============================================================
// Tensor-core flash ConsMax attention, single fp16, exp2 domain,
// 3-stage cp.async, deferred-wait. Score frags initialized with
// the additive mask (MMA accumulates on top).
// 128 q-rows/CTA, 8 warps, Bc=64. Emits single-fp16 C.
// ============================================================
#define LDV 72
#define A_AS (64 * LDV)
#define A_STAGE_B (2 * A_AS * 2)            // K, V (18432 B)
#define A_MASK_OFF (3 * A_STAGE_B)          // 55296
#define A_SMEM_B (A_MASK_OFF + 3 * 256)     // 56064

__global__ __launch_bounds__(256) void consmax_attn_mma(
    const __half* __restrict__ Q, const __half* __restrict__ K,
    const __half* __restrict__ V,
    const float* __restrict__ madd, const float* __restrict__ gamma,
    __half* __restrict__ Cq)
{
    extern __shared__ char smem[];
    const uint32_t sb = smem_u32(smem);

    const int qb = blockIdx.x, h = blockIdx.y, b = blockIdx.z;
    const int t = threadIdx.x, lane = t & 31, w = t >> 5;
    const int row0 = b * S_ + qb * 128;

    // ---- Q fragments straight from global (A-frag layout) ----
    uint32_t qf[4][4];
    {
        const int fr = lane >> 2;
        const int fc = (lane & 3) * 2;
        const size_t base = (size_t)(row0 + w * 16 + fr) * HID_ + h * HD_ + fc;
#pragma unroll
        for (int ks = 0; ks < 4; ks++) {
            const size_t g = base + ks * 16;
            qf[ks][0] = *(const uint32_t*)(Q + g);
            qf[ks][1] = *(const uint32_t*)(Q + g + 8 * HID_);
            qf[ks][2] = *(const uint32_t*)(Q + g + 8);
            qf[ks][3] = *(const uint32_t*)(Q + g + 8 * HID_ + 8);
        }
    }

    float m0 = -1e30f, m1 = -1e30f;
    float O[8][4];
#pragma unroll
    for (int nt = 0; nt < 8; nt++)
#pragma unroll
        for (int r = 0; r < 4; r++) O[nt][r] = 0.0f;

#define A_LOAD(s, j0) do {                                                        \
        uint32_t st = sb + (uint32_t)(s) * A_STAGE_B;                             \
        _Pragma("unroll")                                                         \
        for (int i2 = 0; i2 < 2; i2++) {                                          \
            int u = t + 256 * i2;                                                 \
            int r = u >> 3, seg = u & 7;                                          \
            const size_t g = (size_t)(b * S_ + (j0) + r) * HID_ + h * HD_ + seg * 8; \
            uint32_t so = (uint32_t)((r * LDV + seg * 8) * 2);                    \
            CP16(st + 0 * A_AS * 2 + so, K + g);                                  \
            CP16(st + 1 * A_AS * 2 + so, V + g);                                  \
        }                                                                         \
        if (t < 16)                                                               \
            CP16(sb + A_MASK_OFF + (uint32_t)(s) * 256 + t * 16,                  \
                 madd + (size_t)b * S_ + (j0) + t * 4);                           \
    } while (0)

    const int NCH = S_ / 64;               // 32 iterations
    A_LOAD(0, 0);  CP_COMMIT();
    A_LOAD(1, 64); CP_COMMIT();
    CP_WAIT1();                            // stage 0 ready

    int stage = 0;
    for (int it = 0; it < NCH; it++) {
        __syncthreads();

        if (it + 2 < NCH) { A_LOAD((it + 2) % 3, (it + 2) * 64); CP_COMMIT(); }

        const uint32_t st  = sb + (uint32_t)stage * A_STAGE_B;
        const uint32_t kB  = st;
        const uint32_t vB  = st + 1 * A_AS * 2;
        const float* smask = (const float*)(smem + A_MASK_OFF + stage * 256);
        stage = stage == 2 ? 0 : stage + 1;

        // ---- init score frags with mask, then S2 += log2e*(Q K^T)/8 ----
        float sc[8][4];
#pragma unroll
        for (int nt = 0; nt < 8; nt++) {
            int col = nt * 8 + (lane & 3) * 2;
            float ma = smask[col], mb2 = smask[col + 1];
            sc[nt][0] = ma; sc[nt][1] = mb2;
            sc[nt][2] = ma; sc[nt][3] = mb2;
        }

#pragma unroll
        for (int ks = 0; ks < 4; ks++) {
            uint32_t bh[4][4];
#pragma unroll
            for (int nb = 0; nb < 4; nb++) {
                uint32_t addr = (uint32_t)(((nb * 16 + (lane >> 4) * 8 + (lane & 7)) * LDV
                                            + ks * 16 + ((lane >> 3) & 1) * 8) * 2);
                ldsm_x4(kB + addr, bh[nb][0], bh[nb][1], bh[nb][2], bh[nb][3]);
            }
#pragma unroll
            for (int nb = 0; nb < 4; nb++) {
                mma16816(sc[2*nb],   qf[ks][0], qf[ks][1], qf[ks][2], qf[ks][3], bh[nb][0], bh[nb][1]);
                mma16816(sc[2*nb+1], qf[ks][0], qf[ks][1], qf[ks][2], qf[ks][3], bh[nb][2], bh[nb][3]);
            }
        }

        // ---- running rowmax (log2 domain) ----
        float mn0 = m0, mn1 = m1;
#pragma unroll
        for (int nt = 0; nt < 8; nt++) {
            mn0 = fmaxf(mn0, fmaxf(sc[nt][0], sc[nt][1]));
            mn1 = fmaxf(mn1, fmaxf(sc[nt][2], sc[nt][3]));
        }
        mn0 = fmaxf(mn0, __shfl_xor_sync(0xffffffffu, mn0, 1));
        mn0 = fmaxf(mn0, __shfl_xor_sync(0xffffffffu, mn0, 2));
        mn1 = fmaxf(mn1, __shfl_xor_sync(0xffffffffu, mn1, 1));
        mn1 = fmaxf(mn1, __shfl_xor_sync(0xffffffffu, mn1, 2));
        float f0 = ex2(m0 - mn0), f1 = ex2(m1 - mn1);
        m0 = mn0; m1 = mn1;

        // ---- P = exp2(s2 - m2) as single fp16 A-frags ----
        uint32_t pa[4][4];
#pragma unroll
        for (int ks = 0; ks < 4; ks++) {
            pa[ks][0] = pack_h2(ex2(sc[2*ks][0] - m0),   ex2(sc[2*ks][1] - m0));
            pa[ks][1] = pack_h2(ex2(sc[2*ks][2] - m1),   ex2(sc[2*ks][3] - m1));
            pa[ks][2] = pack_h2(ex2(sc[2*ks+1][0] - m0), ex2(sc[2*ks+1][1] - m0));
            pa[ks][3] = pack_h2(ex2(sc[2*ks+1][2] - m1), ex2(sc[2*ks+1][3] - m1));
        }

        // ---- rescale O ----
#pragma unroll
        for (int nt = 0; nt < 8; nt++) {
            O[nt][0] *= f0; O[nt][1] *= f0; O[nt][2] *= f1; O[nt][3] *= f1;
        }

        // ---- O += P V (1 MMA per tile) ----
#pragma unroll
        for (int ks = 0; ks < 4; ks++) {
            uint32_t vf[4][4];
#pragma unroll
            for (int db = 0; db < 4; db++) {
                uint32_t addr = (uint32_t)(((ks * 16 + ((lane >> 3) & 1) * 8 + (lane & 7)) * LDV
                                            + db * 16 + (lane >> 4) * 8) * 2);
                ldsm_x4_trans(vB + addr, vf[db][0], vf[db][1], vf[db][2], vf[db][3]);
            }
#pragma unroll
            for (int db = 0; db < 4; db++) {
                mma16816(O[2*db],   pa[ks][0], pa[ks][1], pa[ks][2], pa[ks][3], vf[db][0], vf[db][1]);
                mma16816(O[2*db+1], pa[ks][0], pa[ks][1], pa[ks][2], pa[ks][3], vf[db][2], vf[db][3]);
            }
        }
        CP_WAIT1();                        // next stage ready; hidden behind this chunk's work
    }

    // ---- epilogue: O/gamma -> single fp16 ----
    const float ig = 1.0f / gamma[0];
#pragma unroll
    for (int nt = 0; nt < 8; nt++) {
        int r = row0 + w * 16 + (lane >> 2);
        int col = h * HD_ + nt * 8 + (lane & 3) * 2;
        *(uint32_t*)&Cq[(size_t)r * HID_ + col]       = pack_h2(O[nt][0] * ig, O[nt][1] * ig);
        *(uint32_t*)&Cq[(size_t)(r + 8) * HID_ + col] = pack_h2(O[nt][2] * ig, O[nt][3] * ig);
    }
}

// ============================================================
// Launch
// ============================================================
extern "C" void kernel_launch(void* const* d_in, const int* in_sizes, int n_in,
                              void* d_out, int out_size)
{
    (void)in_sizes; (void)n_in; (void)out_size;
    const float* X    = (const float*)d_in[0];
    const float* mask = (const float*)d_in[1];
    const float* Wq   = (const float*)d_in[2];
    const float* bq   = (const float*)d_in[3];
    const float* Wk   = (const float*)d_in[4];
    const float* bk   = (const float*)d_in[5];
    const float* Wv   = (const float*)d_in[6];
    const float* bv   = (const float*)d_in[7];
    const float* Wo   = (const float*)d_in[8];
    const float* bo   = (const float*)d_in[9];
    const float* gamma = (const float*)d_in[11];   // beta (d_in[10]) cancels exactly
    float* out = (float*)d_out;

    __half *xh, *wh, *qp, *kp, *vp, *cp;
    float* mad;
    cudaGetSymbolAddress((void**)&xh,  g_Xh);
    cudaGetSymbolAddress((void**)&wh,  g_Wh);
    cudaGetSymbolAddress((void**)&qp,  g_Q);
    cudaGetSymbolAddress((void**)&kp,  g_K);
    cudaGetSymbolAddress((void**)&vp,  g_V);
    cudaGetSymbolAddress((void**)&cp,  g_C);
    cudaGetSymbolAddress((void**)&mad, g_Madd);

    cudaFuncSetAttribute(gemm_mma_f16<true>,  cudaFuncAttributeMaxDynamicSharedMemorySize, G_SMEM_B);
    cudaFuncSetAttribute(gemm_mma_f16<false>, cudaFuncAttributeMaxDynamicSharedMemorySize, G_SMEM_B);
    cudaFuncSetAttribute(consmax_attn_mma,    cudaFuncAttributeMaxDynamicSharedMemorySize, A_SMEM_B);

    cvt_h<<<(MTOT * HID_ / 4 + 255) / 256, 256>>>(X, xh, MTOT * HID_ / 4);
    cvt_h4<<<(4 * WN_ / 4) / 256, 256>>>(Wq, Wk, Wv, Wo, wh);
    msk_prep<<<(MTOT + 255) / 256, 256>>>(mask, mad, MTOT);

    // fused QKV projection (1-term): z = 0(Q, x log2e/8), 1(K), 2(V)
    dim3 gq(HID_ / 128, MTOT / 128, 3);
    gemm_mma_f16<true><<<gq, 256, G_SMEM_B>>>(xh, wh,
                                              bq, bk, bv, nullptr,
                                              qp, kp, vp,
                                              MTOT, HID_, HID_, 0.125f * LOG2E);

    dim3 ga(S_ / 128, NH_, B_);        // (16, 16, 2)
    consmax_attn_mma<<<ga, 256, A_SMEM_B>>>(qp, kp, vp, mad, gamma, cp);

    // output projection (1-term, C single fp16) -> fp32 out
    dim3 go(HID_ / 128, MTOT / 128, 1);
    gemm_mma_f16<false><<<go, 256, G_SMEM_B>>>(cp, wh + 3 * (size_t)WN_,
                                               bo, nullptr, nullptr,
                                               out, nullptr, nullptr, nullptr,
                                               MTOT, HID_, HID_, 1.0f);
}

// round 14
// speedup vs baseline: 1.8625x; 1.0872x over previous
#include <cuda_runtime.h>
#include <cuda_fp16.h>
#include <math.h>
#include <stdint.h>

#define B_    2
#define S_    2048
#define HID_  1024
#define NH_   16
#define HD_   64
#define MTOT  (B_ * S_)
#define WN_   (HID_ * HID_)
#define LOG2E 1.4426950408889634f

// ---------------- scratch (static device allocations) ----------------
__device__ __half g_Xh[MTOT * HID_];
__device__ __half g_Wh[4 * WN_];
__device__ __half g_Q[MTOT * HID_];
__device__ __half g_K[MTOT * HID_];
__device__ __half g_V[MTOT * HID_];
__device__ __half g_C[MTOT * HID_];
__device__ float  g_Madd[MTOT];

// ---------------- helpers (baseline PTX only) ----------------
__device__ __forceinline__ uint32_t smem_u32(const void* p) {
    uint32_t a;
    asm("{ .reg .u64 t; cvta.to.shared.u64 t, %1; cvt.u32.u64 %0, t; }" : "=r"(a) : "l"(p));
    return a;
}
__device__ __forceinline__ void ldsm_x4(uint32_t addr, uint32_t& r0, uint32_t& r1,
                                        uint32_t& r2, uint32_t& r3) {
    asm volatile("ldmatrix.sync.aligned.m8n8.x4.shared.b16 {%0,%1,%2,%3}, [%4];"
                 : "=r"(r0), "=r"(r1), "=r"(r2), "=r"(r3) : "r"(addr));
}
__device__ __forceinline__ void ldsm_x4_trans(uint32_t addr, uint32_t& r0, uint32_t& r1,
                                              uint32_t& r2, uint32_t& r3) {
    asm volatile("ldmatrix.sync.aligned.m8n8.x4.trans.shared.b16 {%0,%1,%2,%3}, [%4];"
                 : "=r"(r0), "=r"(r1), "=r"(r2), "=r"(r3) : "r"(addr));
}
__device__ __forceinline__ void mma16816(float* c, uint32_t a0, uint32_t a1,
                                         uint32_t a2, uint32_t a3,
                                         uint32_t b0, uint32_t b1) {
    asm volatile(
        "mma.sync.aligned.m16n8k16.row.col.f32.f16.f16.f32 "
        "{%0,%1,%2,%3}, {%4,%5,%6,%7}, {%8,%9}, {%0,%1,%2,%3};"
        : "+f"(c[0]), "+f"(c[1]), "+f"(c[2]), "+f"(c[3])
        : "r"(a0), "r"(a1), "r"(a2), "r"(a3), "r"(b0), "r"(b1));
}
__device__ __forceinline__ uint32_t pack_h2(float a, float b) {
    __half2 h = __floats2half2_rn(a, b);
    return *(uint32_t*)&h;
}
__device__ __forceinline__ float ex2(float x) {
    float y;
    asm("ex2.approx.ftz.f32 %0, %1;" : "=f"(y) : "f"(x));
    return y;
}
#define CP16(dst, src) \
    asm volatile("cp.async.cg.shared.global [%0], [%1], 16;" :: "r"(dst), "l"(src))
#define CP_COMMIT() asm volatile("cp.async.commit_group;")
#define CP_WAIT1()  asm volatile("cp.async.wait_group 1;")

// ---------------- fused prep: X->h, 4xW->h, mask->madd ----------------
__global__ __launch_bounds__(256) void prep_all(
    const float* __restrict__ X,
    const float* __restrict__ w0, const float* __restrict__ w1,
    const float* __restrict__ w2, const float* __restrict__ w3,
    const float* __restrict__ mask,
    __half* __restrict__ xh, __half* __restrict__ wh,
    float* __restrict__ madd)
{
    const int NX = MTOT * HID_ / 4;        // 1048576
    const int NW = WN_ / 4;                // 262144 per weight
    int i = blockIdx.x * blockDim.x + threadIdx.x;
    if (i < NX) {
        float4 v = ((const float4*)X)[i];
        ((uint2*)xh)[i] = make_uint2(pack_h2(v.x, v.y), pack_h2(v.z, v.w));
        return;
    }
    i -= NX;
    if (i < 4 * NW) {
        int sel = i / NW;
        int j   = i - sel * NW;
        const float* src = sel == 0 ? w0 : (sel == 1 ? w1 : (sel == 2 ? w2 : w3));
        float4 v = ((const float4*)src)[j];
        ((uint2*)wh)[i] = make_uint2(pack_h2(v.x, v.y), pack_h2(v.z, v.w));
        return;
    }
    i -= 4 * NW;
    if (i < MTOT / 4) {
        float4 m = ((const float4*)mask)[i];
        float4 r;
        r.x = (1.0f - m.x) * (-10000.0f * LOG2E);
        r.y = (1.0f - m.y) * (-10000.0f * LOG2E);
        r.z = (1.0f - m.z) * (-10000.0f * LOG2E);
        r.w = (1.0f - m.w) * (-10000.0f * LOG2E);
        ((float4*)madd)[i] = r;
    }
}

// ============================================================
// Tensor-core GEMM, 3-stage cp.async, register-double-buffered
// fragments: MMA after each barrier uses frags loaded before it.
// Single fp16 A and W: C = (A @ W^T + bias) * oscale.
// grid.z selects among up to 3 (W, bias, dest) sets.
// ============================================================
#define LDA 40
#define G_AS (128 * LDA)
#define G_STAGE_B (2 * G_AS * 2)          // A, W  (20480 B)
#define G_SMEM_B (3 * G_STAGE_B)          // 3 stages (61440 B)

template<bool OUT16>
__global__ __launch_bounds__(256) void gemm_mma_f16(
    const __half* __restrict__ A,
    const __half* __restrict__ Whb,
    const float* __restrict__ bias0, const float* __restrict__ bias1,
    const float* __restrict__ bias2,
    float* __restrict__ C,
    __half* __restrict__ C0, __half* __restrict__ C1, __half* __restrict__ C2,
    int M, int N, int K, float osc0)
{
    extern __shared__ char smem[];
    const uint32_t sb = smem_u32(smem);

    const int z = blockIdx.z;
    const __half* Bh = Whb + (size_t)z * WN_;
    const float* bias = z == 0 ? bias0 : (z == 1 ? bias1 : bias2);
    __half* Cd = z == 0 ? C0 : (z == 1 ? C1 : C2);
    const float oscale = z == 0 ? osc0 : 1.0f;

    const int t    = threadIdx.x;
    const int lane = t & 31;
    const int wid  = t >> 5;
    const int wm   = (wid & 1) * 64;
    const int wn   = (wid >> 1) * 32;
    const int bm   = blockIdx.y * 128;
    const int bn   = blockIdx.x * 128;

    float acc[4][4][4];
#pragma unroll
    for (int i = 0; i < 4; i++)
#pragma unroll
        for (int j = 0; j < 4; j++)
#pragma unroll
            for (int r = 0; r < 4; r++) acc[i][j][r] = 0.0f;

    const int lr = t >> 2;
    const int lc = (t & 3) * 8;

    const uint32_t aOff = (uint32_t)(((wm + (lane & 15)) * LDA + (lane >> 4) * 8) * 2);
    const uint32_t bOff = (uint32_t)(((wn + (lane >> 4) * 8 + (lane & 7)) * LDA + ((lane >> 3) & 1) * 8) * 2);

    uint32_t afr[2][4][4], bfr[2][8];

#define G_LOAD(s, k0) do {                                                        \
        uint32_t st = sb + (uint32_t)(s) * G_STAGE_B;                             \
        _Pragma("unroll")                                                         \
        for (int bch = 0; bch < 2; bch++) {                                       \
            int r = lr + bch * 64;                                                \
            size_t ga = (size_t)(bm + r) * K + (k0) + lc;                         \
            size_t gb = (size_t)(bn + r) * K + (k0) + lc;                         \
            uint32_t so = (uint32_t)((r * LDA + lc) * 2);                         \
            CP16(st + 0 * G_AS * 2 + so, A + ga);                                 \
            CP16(st + 1 * G_AS * 2 + so, Bh + gb);                                \
        }                                                                         \
    } while (0)

#define LDFR(buf, stg, kb) do {                                                   \
        uint32_t _aB = sb + (uint32_t)(stg) * G_STAGE_B;                          \
        uint32_t _bB = _aB + G_AS * 2;                                            \
        _Pragma("unroll")                                                         \
        for (int pr = 0; pr < 2; pr++) {                                          \
            uint32_t ba = bOff + (uint32_t)(pr * 16 * LDA * 2) + (kb);            \
            ldsm_x4(_bB + ba, bfr[buf][pr*4+0], bfr[buf][pr*4+1],                 \
                              bfr[buf][pr*4+2], bfr[buf][pr*4+3]);                \
        }                                                                         \
        _Pragma("unroll")                                                         \
        for (int mt = 0; mt < 4; mt++) {                                          \
            uint32_t aa = aOff + (uint32_t)(mt * 16 * LDA * 2) + (kb);            \
            ldsm_x4(_aB + aa, afr[buf][mt][0], afr[buf][mt][1],                   \
                              afr[buf][mt][2], afr[buf][mt][3]);                  \
        }                                                                         \
    } while (0)

#define MMASET(buf) do {                                                          \
        _Pragma("unroll")                                                         \
        for (int mt = 0; mt < 4; mt++)                                            \
            _Pragma("unroll")                                                     \
            for (int nt = 0; nt < 4; nt++) {                                      \
                const int pr = nt >> 1, hf = (nt & 1) * 2;                        \
                mma16816(acc[mt][nt],                                             \
                         afr[buf][mt][0], afr[buf][mt][1],                        \
                         afr[buf][mt][2], afr[buf][mt][3],                        \
                         bfr[buf][pr*4 + hf], bfr[buf][pr*4 + hf + 1]);           \
            }                                                                     \
    } while (0)

    const int NK = K / 32;                 // 32 iterations
    G_LOAD(0, 0);  CP_COMMIT();
    G_LOAD(1, 32); CP_COMMIT();
    CP_WAIT1();
    __syncthreads();                       // stage 0 published
    LDFR(0, 0, 0);                         // ks=0 frags of stage 0

    int stage = 0;
    for (int it = 0; it < NK; it++) {
        LDFR(1, stage, 32);                // ks=1 frags (independent of MMAs below)
        MMASET(0);                         // frags resident since before the barrier

        if (it + 2 < NK) G_LOAD((it + 2) % 3, (it + 2) * 32);
        CP_COMMIT();

        MMASET(1);

        CP_WAIT1();                        // stage it+1 data arrived
        __syncthreads();                   // publish; all warps done reading stage it
        stage = stage == 2 ? 0 : stage + 1;
        if (it + 1 < NK) LDFR(0, stage, 0);  // prefetch next ks=0 across the barrier
    }

#pragma unroll
    for (int mt = 0; mt < 4; mt++) {
#pragma unroll
        for (int nt = 0; nt < 4; nt++) {
            int row = bm + wm + mt * 16 + (lane >> 2);
            int col = bn + wn + nt * 8 + (lane & 3) * 2;
            float2 bvv = *(const float2*)&bias[col];
            float v0x = (acc[mt][nt][0] + bvv.x) * oscale, v0y = (acc[mt][nt][1] + bvv.y) * oscale;
            float v1x = (acc[mt][nt][2] + bvv.x) * oscale, v1y = (acc[mt][nt][3] + bvv.y) * oscale;
            if (OUT16) {
                *(uint32_t*)&Cd[(size_t)row * N + col]       = pack_h2(v0x, v0y);
                *(uint32_t*)&Cd[(size_t)(row + 8) * N + col] = pack_h2(v1x, v1y);
            } else {
                *(float2*)&C[(size_t)row * N + col] = make_float2(v0x, v0y);
                *(float2*)&C[(size_t)(row + 8) * N + col] = make_float2(v1x, v1y);
            }
        }
    }
}

// ============================================================
// Tensor-core flash ConsMax attention (unchanged from R13).
// Single fp16, exp2 domain, 3-stage cp.async deferred-wait.
// 128 q-rows/CTA, 8 warps, Bc=64. Emits single-fp16 C.
// ============================================================
#define LDV 72
#define A_AS (64 * LDV)
#define A_STAGE_B (2 * A_AS * 2)            // K, V (18432 B)
#define A_MASK_OFF (3 * A_STAGE_B)          // 55296
#define A_SMEM_B (A_MASK_OFF + 3 * 256)     // 56064

__global__ __launch_bounds__(256) void consmax_attn_mma(
    const __half* __restrict__ Q, const __half* __restrict__ K,
    const __half* __restrict__ V,
    const float* __restrict__ madd, const float* __restrict__ gamma,
    __half* __restrict__ Cq)
{
    extern __shared__ char smem[];
    const uint32_t sb = smem_u32(smem);

    const int qb = blockIdx.x, h = blockIdx.y, b = blockIdx.z;
    const int t = threadIdx.x, lane = t & 31, w = t >> 5;
    const int row0 = b * S_ + qb * 128;

    uint32_t qf[4][4];
    {
        const int fr = lane >> 2;
        const int fc = (lane & 3) * 2;
        const size_t base = (size_t)(row0 + w * 16 + fr) * HID_ + h * HD_ + fc;
#pragma unroll
        for (int ks = 0; ks < 4; ks++) {
            const size_t g = base + ks * 16;
            qf[ks][0] = *(const uint32_t*)(Q + g);
            qf[ks][1] = *(const uint32_t*)(Q + g + 8 * HID_);
            qf[ks][2] = *(const uint32_t*)(Q + g + 8);
            qf[ks][3] = *(const uint32_t*)(Q + g + 8 * HID_ + 8);
        }
    }

    float m0 = -1e30f, m1 = -1e30f;
    float O[8][4];
#pragma unroll
    for (int nt = 0; nt < 8; nt++)
#pragma unroll
        for (int r = 0; r < 4; r++) O[nt][r] = 0.0f;

#define A_LOAD(s, j0) do {                                                        \
        uint32_t st = sb + (uint32_t)(s) * A_STAGE_B;                             \
        _Pragma("unroll")                                                         \
        for (int i2 = 0; i2 < 2; i2++) {                                          \
            int u = t + 256 * i2;                                                 \
            int r = u >> 3, seg = u & 7;                                          \
            const size_t g = (size_t)(b * S_ + (j0) + r) * HID_ + h * HD_ + seg * 8; \
            uint32_t so = (uint32_t)((r * LDV + seg * 8) * 2);                    \
            CP16(st + 0 * A_AS * 2 + so, K + g);                                  \
            CP16(st + 1 * A_AS * 2 + so, V + g);                                  \
        }                                                                         \
        if (t < 16)                                                               \
            CP16(sb + A_MASK_OFF + (uint32_t)(s) * 256 + t * 16,                  \
                 madd + (size_t)b * S_ + (j0) + t * 4);                           \
    } while (0)

    const int NCH = S_ / 64;
    A_LOAD(0, 0);  CP_COMMIT();
    A_LOAD(1, 64); CP_COMMIT();
    CP_WAIT1();

    int stage = 0;
    for (int it = 0; it < NCH; it++) {
        __syncthreads();

        if (it + 2 < NCH) { A_LOAD((it + 2) % 3, (it + 2) * 64); CP_COMMIT(); }

        const uint32_t st  = sb + (uint32_t)stage * A_STAGE_B;
        const uint32_t kB  = st;
        const uint32_t vB  = st + 1 * A_AS * 2;
        const float* smask = (const float*)(smem + A_MASK_OFF + stage * 256);
        stage = stage == 2 ? 0 : stage + 1;

        float sc[8][4];
#pragma unroll
        for (int nt = 0; nt < 8; nt++) {
            int col = nt * 8 + (lane & 3) * 2;
            float ma = smask[col], mb2 = smask[col + 1];
            sc[nt][0] = ma; sc[nt][1] = mb2;
            sc[nt][2] = ma; sc[nt][3] = mb2;
        }

#pragma unroll
        for (int ks = 0; ks < 4; ks++) {
            uint32_t bh[4][4];
#pragma unroll
            for (int nb = 0; nb < 4; nb++) {
                uint32_t addr = (uint32_t)(((nb * 16 + (lane >> 4) * 8 + (lane & 7)) * LDV
                                            + ks * 16 + ((lane >> 3) & 1) * 8) * 2);
                ldsm_x4(kB + addr, bh[nb][0], bh[nb][1], bh[nb][2], bh[nb][3]);
            }
#pragma unroll
            for (int nb = 0; nb < 4; nb++) {
                mma16816(sc[2*nb],   qf[ks][0], qf[ks][1], qf[ks][2], qf[ks][3], bh[nb][0], bh[nb][1]);
                mma16816(sc[2*nb+1], qf[ks][0], qf[ks][1], qf[ks][2], qf[ks][3], bh[nb][2], bh[nb][3]);
            }
        }

        float mn0 = m0, mn1 = m1;
#pragma unroll
        for (int nt = 0; nt < 8; nt++) {
            mn0 = fmaxf(mn0, fmaxf(sc[nt][0], sc[nt][1]));
            mn1 = fmaxf(mn1, fmaxf(sc[nt][2], sc[nt][3]));
        }
        mn0 = fmaxf(mn0, __shfl_xor_sync(0xffffffffu, mn0, 1));
        mn0 = fmaxf(mn0, __shfl_xor_sync(0xffffffffu, mn0, 2));
        mn1 = fmaxf(mn1, __shfl_xor_sync(0xffffffffu, mn1, 1));
        mn1 = fmaxf(mn1, __shfl_xor_sync(0xffffffffu, mn1, 2));
        float f0 = ex2(m0 - mn0), f1 = ex2(m1 - mn1);
        m0 = mn0; m1 = mn1;

        uint32_t pa[4][4];
#pragma unroll
        for (int ks = 0; ks < 4; ks++) {
            pa[ks][0] = pack_h2(ex2(sc[2*ks][0] - m0),   ex2(sc[2*ks][1] - m0));
            pa[ks][1] = pack_h2(ex2(sc[2*ks][2] - m1),   ex2(sc[2*ks][3] - m1));
            pa[ks][2] = pack_h2(ex2(sc[2*ks+1][0] - m0), ex2(sc[2*ks+1][1] - m0));
            pa[ks][3] = pack_h2(ex2(sc[2*ks+1][2] - m1), ex2(sc[2*ks+1][3] - m1));
        }

#pragma unroll
        for (int nt = 0; nt < 8; nt++) {
            O[nt][0] *= f0; O[nt][1] *= f0; O[nt][2] *= f1; O[nt][3] *= f1;
        }

#pragma unroll
        for (int ks = 0; ks < 4; ks++) {
            uint32_t vf[4][4];
#pragma unroll
            for (int db = 0; db < 4; db++) {
                uint32_t addr = (uint32_t)(((ks * 16 + ((lane >> 3) & 1) * 8 + (lane & 7)) * LDV
                                            + db * 16 + (lane >> 4) * 8) * 2);
                ldsm_x4_trans(vB + addr, vf[db][0], vf[db][1], vf[db][2], vf[db][3]);
            }
#pragma unroll
            for (int db = 0; db < 4; db++) {
                mma16816(O[2*db],   pa[ks][0], pa[ks][1], pa[ks][2], pa[ks][3], vf[db][0], vf[db][1]);
                mma16816(O[2*db+1], pa[ks][0], pa[ks][1], pa[ks][2], pa[ks][3], vf[db][2], vf[db][3]);
            }
        }
        CP_WAIT1();
    }

    const float ig = 1.0f / gamma[0];
#pragma unroll
    for (int nt = 0; nt < 8; nt++) {
        int r = row0 + w * 16 + (lane >> 2);
        int col = h * HD_ + nt * 8 + (lane & 3) * 2;
        *(uint32_t*)&Cq[(size_t)r * HID_ + col]       = pack_h2(O[nt][0] * ig, O[nt][1] * ig);
        *(uint32_t*)&Cq[(size_t)(r + 8) * HID_ + col] = pack_h2(O[nt][2] * ig, O[nt][3] * ig);
    }
}

// ============================================================
// Launch
// ============================================================
extern "C" void kernel_launch(void* const* d_in, const int* in_sizes, int n_in,
                              void* d_out, int out_size)
{
    (void)in_sizes; (void)n_in; (void)out_size;
    const float* X    = (const float*)d_in[0];
    const float* mask = (const float*)d_in[1];
    const float* Wq   = (const float*)d_in[2];
    const float* bq   = (const float*)d_in[3];
    const float* Wk   = (const float*)d_in[4];
    const float* bk   = (const float*)d_in[5];
    const float* Wv   = (const float*)d_in[6];
    const float* bv   = (const float*)d_in[7];
    const float* Wo   = (const float*)d_in[8];
    const float* bo   = (const float*)d_in[9];
    const float* gamma = (const float*)d_in[11];   // beta (d_in[10]) cancels exactly
    float* out = (float*)d_out;

    __half *xh, *wh, *qp, *kp, *vp, *cp;
    float* mad;
    cudaGetSymbolAddress((void**)&xh,  g_Xh);
    cudaGetSymbolAddress((void**)&wh,  g_Wh);
    cudaGetSymbolAddress((void**)&qp,  g_Q);
    cudaGetSymbolAddress((void**)&kp,  g_K);
    cudaGetSymbolAddress((void**)&vp,  g_V);
    cudaGetSymbolAddress((void**)&cp,  g_C);
    cudaGetSymbolAddress((void**)&mad, g_Madd);

    cudaFuncSetAttribute(gemm_mma_f16<true>,  cudaFuncAttributeMaxDynamicSharedMemorySize, G_SMEM_B);
    cudaFuncSetAttribute(gemm_mma_f16<false>, cudaFuncAttributeMaxDynamicSharedMemorySize, G_SMEM_B);
    cudaFuncSetAttribute(consmax_attn_mma,    cudaFuncAttributeMaxDynamicSharedMemorySize, A_SMEM_B);

    const int NPREP = MTOT * HID_ / 4 + 4 * (WN_ / 4) + MTOT / 4;
    prep_all<<<(NPREP + 255) / 256, 256>>>(X, Wq, Wk, Wv, Wo, mask, xh, wh, mad);

    // fused QKV projection (1-term): z = 0(Q, x log2e/8), 1(K), 2(V)
    dim3 gq(HID_ / 128, MTOT / 128, 3);
    gemm_mma_f16<true><<<gq, 256, G_SMEM_B>>>(xh, wh,
                                              bq, bk, bv, nullptr,
                                              qp, kp, vp,
                                              MTOT, HID_, HID_, 0.125f * LOG2E);

    dim3 ga(S_ / 128, NH_, B_);        // (16, 16, 2)
    consmax_attn_mma<<<ga, 256, A_SMEM_B>>>(qp, kp, vp, mad, gamma, cp);

    // output projection (1-term, C single fp16) -> fp32 out
    dim3 go(HID_ / 128, MTOT / 128, 1);
    gemm_mma_f16<false><<<go, 256, G_SMEM_B>>>(cp, wh + 3 * (size_t)WN_,
                                               bo, nullptr, nullptr,
                                               out, nullptr, nullptr, nullptr,
                                               MTOT, HID_, HID_, 1.0f);
}

// round 15
// speedup vs baseline: 1.9427x; 1.0431x over previous
#include <cuda_runtime.h>
#include <cuda_fp16.h>
#include <math.h>
#include <stdint.h>

#define B_    2
#define S_    2048
#define HID_  1024
#define NH_   16
#define HD_   64
#define MTOT  (B_ * S_)
#define WN_   (HID_ * HID_)
#define LOG2E 1.4426950408889634f

// ---------------- scratch (static device allocations) ----------------
__device__ __half g_Xh[MTOT * HID_];
__device__ __half g_Wh[4 * WN_];
__device__ __half g_Q[MTOT * HID_];
__device__ __half g_K[MTOT * HID_];
__device__ __half g_V[MTOT * HID_];
__device__ __half g_C[MTOT * HID_];
__device__ float  g_Madd[MTOT];

// ---------------- helpers (baseline PTX only) ----------------
__device__ __forceinline__ uint32_t smem_u32(const void* p) {
    uint32_t a;
    asm("{ .reg .u64 t; cvta.to.shared.u64 t, %1; cvt.u32.u64 %0, t; }" : "=r"(a) : "l"(p));
    return a;
}
__device__ __forceinline__ void ldsm_x4(uint32_t addr, uint32_t& r0, uint32_t& r1,
                                        uint32_t& r2, uint32_t& r3) {
    asm volatile("ldmatrix.sync.aligned.m8n8.x4.shared.b16 {%0,%1,%2,%3}, [%4];"
                 : "=r"(r0), "=r"(r1), "=r"(r2), "=r"(r3) : "r"(addr));
}
__device__ __forceinline__ void ldsm_x4_trans(uint32_t addr, uint32_t& r0, uint32_t& r1,
                                              uint32_t& r2, uint32_t& r3) {
    asm volatile("ldmatrix.sync.aligned.m8n8.x4.trans.shared.b16 {%0,%1,%2,%3}, [%4];"
                 : "=r"(r0), "=r"(r1), "=r"(r2), "=r"(r3) : "r"(addr));
}
__device__ __forceinline__ void mma16816(float* c, uint32_t a0, uint32_t a1,
                                         uint32_t a2, uint32_t a3,
                                         uint32_t b0, uint32_t b1) {
    asm volatile(
        "mma.sync.aligned.m16n8k16.row.col.f32.f16.f16.f32 "
        "{%0,%1,%2,%3}, {%4,%5,%6,%7}, {%8,%9}, {%0,%1,%2,%3};"
        : "+f"(c[0]), "+f"(c[1]), "+f"(c[2]), "+f"(c[3])
        : "r"(a0), "r"(a1), "r"(a2), "r"(a3), "r"(b0), "r"(b1));
}
__device__ __forceinline__ uint32_t pack_h2(float a, float b) {
    __half2 h = __floats2half2_rn(a, b);
    return *(uint32_t*)&h;
}
__device__ __forceinline__ float ex2(float x) {
    float y;
    asm("ex2.approx.ftz.f32 %0, %1;" : "=f"(y) : "f"(x));
    return y;
}
#define CP16(dst, src) \
    asm volatile("cp.async.cg.shared.global [%0], [%1], 16;" :: "r"(dst), "l"(src))
#define CP_COMMIT() asm volatile("cp.async.commit_group;")
#define CP_WAIT1()  asm volatile("cp.async.wait_group 1;")

// ---------------- fused prep: X->h, 4xW->h, mask->madd ----------------
__global__ __launch_bounds__(256) void prep_all(
    const float* __restrict__ X,
    const float* __restrict__ w0, const float* __restrict__ w1,
    const float* __restrict__ w2, const float* __restrict__ w3,
    const float* __restrict__ mask,
    __half* __restrict__ xh, __half* __restrict__ wh,
    float* __restrict__ madd)
{
    const int NX = MTOT * HID_ / 4;
    const int NW = WN_ / 4;
    int i = blockIdx.x * blockDim.x + threadIdx.x;
    if (i < NX) {
        float4 v = ((const float4*)X)[i];
        ((uint2*)xh)[i] = make_uint2(pack_h2(v.x, v.y), pack_h2(v.z, v.w));
        return;
    }
    i -= NX;
    if (i < 4 * NW) {
        int sel = i / NW;
        int j   = i - sel * NW;
        const float* src = sel == 0 ? w0 : (sel == 1 ? w1 : (sel == 2 ? w2 : w3));
        float4 v = ((const float4*)src)[j];
        ((uint2*)wh)[i] = make_uint2(pack_h2(v.x, v.y), pack_h2(v.z, v.w));
        return;
    }
    i -= 4 * NW;
    if (i < MTOT / 4) {
        float4 m = ((const float4*)mask)[i];
        float4 r;
        r.x = (1.0f - m.x) * (-10000.0f * LOG2E);
        r.y = (1.0f - m.y) * (-10000.0f * LOG2E);
        r.z = (1.0f - m.z) * (-10000.0f * LOG2E);
        r.w = (1.0f - m.w) * (-10000.0f * LOG2E);
        ((float4*)madd)[i] = r;
    }
}

// ============================================================
// Tensor-core GEMM, 3-stage cp.async, register-double-buffered
// fragments; capped at 128 regs for 2 CTAs/SM.
// Single fp16 A and W: C = (A @ W^T + bias) * oscale.
// grid.z selects among up to 3 (W, bias, dest) sets.
// ============================================================
#define LDA 40
#define G_AS (128 * LDA)
#define G_STAGE_B (2 * G_AS * 2)          // A, W  (20480 B)
#define G_SMEM_B (3 * G_STAGE_B)          // 3 stages (61440 B)

template<bool OUT16>
__global__ __launch_bounds__(256, 2) void gemm_mma_f16(
    const __half* __restrict__ A,
    const __half* __restrict__ Whb,
    const float* __restrict__ bias0, const float* __restrict__ bias1,
    const float* __restrict__ bias2,
    float* __restrict__ C,
    __half* __restrict__ C0, __half* __restrict__ C1, __half* __restrict__ C2,
    int M, int N, int K, float osc0)
{
    extern __shared__ char smem[];
    const uint32_t sb = smem_u32(smem);

    const int z = blockIdx.z;
    const __half* Bh = Whb + (size_t)z * WN_;
    const float* bias = z == 0 ? bias0 : (z == 1 ? bias1 : bias2);
    __half* Cd = z == 0 ? C0 : (z == 1 ? C1 : C2);
    const float oscale = z == 0 ? osc0 : 1.0f;

    const int t    = threadIdx.x;
    const int lane = t & 31;
    const int wid  = t >> 5;
    const int wm   = (wid & 1) * 64;
    const int wn   = (wid >> 1) * 32;
    const int bm   = blockIdx.y * 128;
    const int bn   = blockIdx.x * 128;

    float acc[4][4][4];
#pragma unroll
    for (int i = 0; i < 4; i++)
#pragma unroll
        for (int j = 0; j < 4; j++)
#pragma unroll
            for (int r = 0; r < 4; r++) acc[i][j][r] = 0.0f;

    const int lr = t >> 2;
    const int lc = (t & 3) * 8;

    const uint32_t aOff = (uint32_t)(((wm + (lane & 15)) * LDA + (lane >> 4) * 8) * 2);
    const uint32_t bOff = (uint32_t)(((wn + (lane >> 4) * 8 + (lane & 7)) * LDA + ((lane >> 3) & 1) * 8) * 2);

    uint32_t afr[2][4][4], bfr[2][8];

#define G_LOAD(s, k0) do {                                                        \
        uint32_t st = sb + (uint32_t)(s) * G_STAGE_B;                             \
        _Pragma("unroll")                                                         \
        for (int bch = 0; bch < 2; bch++) {                                       \
            int r = lr + bch * 64;                                                \
            size_t ga = (size_t)(bm + r) * K + (k0) + lc;                         \
            size_t gb = (size_t)(bn + r) * K + (k0) + lc;                         \
            uint32_t so = (uint32_t)((r * LDA + lc) * 2);                         \
            CP16(st + 0 * G_AS * 2 + so, A + ga);                                 \
            CP16(st + 1 * G_AS * 2 + so, Bh + gb);                                \
        }                                                                         \
    } while (0)

#define LDFR(buf, stg, kb) do {                                                   \
        uint32_t _aB = sb + (uint32_t)(stg) * G_STAGE_B;                          \
        uint32_t _bB = _aB + G_AS * 2;                                            \
        _Pragma("unroll")                                                         \
        for (int pr = 0; pr < 2; pr++) {                                          \
            uint32_t ba = bOff + (uint32_t)(pr * 16 * LDA * 2) + (kb);            \
            ldsm_x4(_bB + ba, bfr[buf][pr*4+0], bfr[buf][pr*4+1],                 \
                              bfr[buf][pr*4+2], bfr[buf][pr*4+3]);                \
        }                                                                         \
        _Pragma("unroll")                                                         \
        for (int mt = 0; mt < 4; mt++) {                                          \
            uint32_t aa = aOff + (uint32_t)(mt * 16 * LDA * 2) + (kb);            \
            ldsm_x4(_aB + aa, afr[buf][mt][0], afr[buf][mt][1],                   \
                              afr[buf][mt][2], afr[buf][mt][3]);                  \
        }                                                                         \
    } while (0)

#define MMASET(buf) do {                                                          \
        _Pragma("unroll")                                                         \
        for (int mt = 0; mt < 4; mt++)                                            \
            _Pragma("unroll")                                                     \
            for (int nt = 0; nt < 4; nt++) {                                      \
                const int pr = nt >> 1, hf = (nt & 1) * 2;                        \
                mma16816(acc[mt][nt],                                             \
                         afr[buf][mt][0], afr[buf][mt][1],                        \
                         afr[buf][mt][2], afr[buf][mt][3],                        \
                         bfr[buf][pr*4 + hf], bfr[buf][pr*4 + hf + 1]);           \
            }                                                                     \
    } while (0)

    const int NK = K / 32;
    G_LOAD(0, 0);  CP_COMMIT();
    G_LOAD(1, 32); CP_COMMIT();
    CP_WAIT1();
    __syncthreads();
    LDFR(0, 0, 0);

    int stage = 0;
    for (int it = 0; it < NK; it++) {
        LDFR(1, stage, 32);
        MMASET(0);

        if (it + 2 < NK) G_LOAD((it + 2) % 3, (it + 2) * 32);
        CP_COMMIT();

        MMASET(1);

        CP_WAIT1();
        __syncthreads();
        stage = stage == 2 ? 0 : stage + 1;
        if (it + 1 < NK) LDFR(0, stage, 0);
    }

#pragma unroll
    for (int mt = 0; mt < 4; mt++) {
#pragma unroll
        for (int nt = 0; nt < 4; nt++) {
            int row = bm + wm + mt * 16 + (lane >> 2);
            int col = bn + wn + nt * 8 + (lane & 3) * 2;
            float2 bvv = *(const float2*)&bias[col];
            float v0x = (acc[mt][nt][0] + bvv.x) * oscale, v0y = (acc[mt][nt][1] + bvv.y) * oscale;
            float v1x = (acc[mt][nt][2] + bvv.x) * oscale, v1y = (acc[mt][nt][3] + bvv.y) * oscale;
            if (OUT16) {
                *(uint32_t*)&Cd[(size_t)row * N + col]       = pack_h2(v0x, v0y);
                *(uint32_t*)&Cd[(size_t)(row + 8) * N + col] = pack_h2(v1x, v1y);
            } else {
                *(float2*)&C[(size_t)row * N + col] = make_float2(v0x, v0y);
                *(float2*)&C[(size_t)(row + 8) * N + col] = make_float2(v1x, v1y);
            }
        }
    }
}

// ============================================================
// Tensor-core flash ConsMax attention (R13 structure).
// Single fp16, exp2 domain, 3-stage cp.async deferred-wait.
// 128 q-rows/CTA, 8 warps, Bc=64. Emits single-fp16 C.
// ============================================================
#define LDV 72
#define A_AS (64 * LDV)
#define A_STAGE_B (2 * A_AS * 2)
#define A_MASK_OFF (3 * A_STAGE_B)
#define A_SMEM_B (A_MASK_OFF + 3 * 256)

__global__ __launch_bounds__(256, 2) void consmax_attn_mma(
    const __half* __restrict__ Q, const __half* __restrict__ K,
    const __half* __restrict__ V,
    const float* __restrict__ madd, const float* __restrict__ gamma,
    __half* __restrict__ Cq)
{
    extern __shared__ char smem[];
    const uint32_t sb = smem_u32(smem);

    const int qb = blockIdx.x, h = blockIdx.y, b = blockIdx.z;
    const int t = threadIdx.x, lane = t & 31, w = t >> 5;
    const int row0 = b * S_ + qb * 128;

    uint32_t qf[4][4];
    {
        const int fr = lane >> 2;
        const int fc = (lane & 3) * 2;
        const size_t base = (size_t)(row0 + w * 16 + fr) * HID_ + h * HD_ + fc;
#pragma unroll
        for (int ks = 0; ks < 4; ks++) {
            const size_t g = base + ks * 16;
            qf[ks][0] = *(const uint32_t*)(Q + g);
            qf[ks][1] = *(const uint32_t*)(Q + g + 8 * HID_);
            qf[ks][2] = *(const uint32_t*)(Q + g + 8);
            qf[ks][3] = *(const uint32_t*)(Q + g + 8 * HID_ + 8);
        }
    }

    float m0 = -1e30f, m1 = -1e30f;
    float O[8][4];
#pragma unroll
    for (int nt = 0; nt < 8; nt++)
#pragma unroll
        for (int r = 0; r < 4; r++) O[nt][r] = 0.0f;

#define A_LOAD(s, j0) do {                                                        \
        uint32_t st = sb + (uint32_t)(s) * A_STAGE_B;                             \
        _Pragma("unroll")                                                         \
        for (int i2 = 0; i2 < 2; i2++) {                                          \
            int u = t + 256 * i2;                                                 \
            int r = u >> 3, seg = u & 7;                                          \
            const size_t g = (size_t)(b * S_ + (j0) + r) * HID_ + h * HD_ + seg * 8; \
            uint32_t so = (uint32_t)((r * LDV + seg * 8) * 2);                    \
            CP16(st + 0 * A_AS * 2 + so, K + g);                                  \
            CP16(st + 1 * A_AS * 2 + so, V + g);                                  \
        }                                                                         \
        if (t < 16)                                                               \
            CP16(sb + A_MASK_OFF + (uint32_t)(s) * 256 + t * 16,                  \
                 madd + (size_t)b * S_ + (j0) + t * 4);                           \
    } while (0)

    const int NCH = S_ / 64;
    A_LOAD(0, 0);  CP_COMMIT();
    A_LOAD(1, 64); CP_COMMIT();
    CP_WAIT1();

    int stage = 0;
    for (int it = 0; it < NCH; it++) {
        __syncthreads();

        if (it + 2 < NCH) { A_LOAD((it + 2) % 3, (it + 2) * 64); CP_COMMIT(); }

        const uint32_t st  = sb + (uint32_t)stage * A_STAGE_B;
        const uint32_t kB  = st;
        const uint32_t vB  = st + 1 * A_AS * 2;
        const float* smask = (const float*)(smem + A_MASK_OFF + stage * 256);
        stage = stage == 2 ? 0 : stage + 1;

        float sc[8][4];
#pragma unroll
        for (int nt = 0; nt < 8; nt++) {
            int col = nt * 8 + (lane & 3) * 2;
            float ma = smask[col], mb2 = smask[col + 1];
            sc[nt][0] = ma; sc[nt][1] = mb2;
            sc[nt][2] = ma; sc[nt][3] = mb2;
        }

#pragma unroll
        for (int ks = 0; ks < 4; ks++) {
            uint32_t bh[4][4];
#pragma unroll
            for (int nb = 0; nb < 4; nb++) {
                uint32_t addr = (uint32_t)(((nb * 16 + (lane >> 4) * 8 + (lane & 7)) * LDV
                                            + ks * 16 + ((lane >> 3) & 1) * 8) * 2);
                ldsm_x4(kB + addr, bh[nb][0], bh[nb][1], bh[nb][2], bh[nb][3]);
            }
#pragma unroll
            for (int nb = 0; nb < 4; nb++) {
                mma16816(sc[2*nb],   qf[ks][0], qf[ks][1], qf[ks][2], qf[ks][3], bh[nb][0], bh[nb][1]);
                mma16816(sc[2*nb+1], qf[ks][0], qf[ks][1], qf[ks][2], qf[ks][3], bh[nb][2], bh[nb][3]);
            }
        }

        float mn0 = m0, mn1 = m1;
#pragma unroll
        for (int nt = 0; nt < 8; nt++) {
            mn0 = fmaxf(mn0, fmaxf(sc[nt][0], sc[nt][1]));
            mn1 = fmaxf(mn1, fmaxf(sc[nt][2], sc[nt][3]));
        }
        mn0 = fmaxf(mn0, __shfl_xor_sync(0xffffffffu, mn0, 1));
        mn0 = fmaxf(mn0, __shfl_xor_sync(0xffffffffu, mn0, 2));
        mn1 = fmaxf(mn1, __shfl_xor_sync(0xffffffffu, mn1, 1));
        mn1 = fmaxf(mn1, __shfl_xor_sync(0xffffffffu, mn1, 2));
        float f0 = ex2(m0 - mn0), f1 = ex2(m1 - mn1);
        m0 = mn0; m1 = mn1;

        uint32_t pa[4][4];
#pragma unroll
        for (int ks = 0; ks < 4; ks++) {
            pa[ks][0] = pack_h2(ex2(sc[2*ks][0] - m0),   ex2(sc[2*ks][1] - m0));
            pa[ks][1] = pack_h2(ex2(sc[2*ks][2] - m1),   ex2(sc[2*ks][3] - m1));
            pa[ks][2] = pack_h2(ex2(sc[2*ks+1][0] - m0), ex2(sc[2*ks+1][1] - m0));
            pa[ks][3] = pack_h2(ex2(sc[2*ks+1][2] - m1), ex2(sc[2*ks+1][3] - m1));
        }

#pragma unroll
        for (int nt = 0; nt < 8; nt++) {
            O[nt][0] *= f0; O[nt][1] *= f0; O[nt][2] *= f1; O[nt][3] *= f1;
        }

#pragma unroll
        for (int ks = 0; ks < 4; ks++) {
            uint32_t vf[4][4];
#pragma unroll
            for (int db = 0; db < 4; db++) {
                uint32_t addr = (uint32_t)(((ks * 16 + ((lane >> 3) & 1) * 8 + (lane & 7)) * LDV
                                            + db * 16 + (lane >> 4) * 8) * 2);
                ldsm_x4_trans(vB + addr, vf[db][0], vf[db][1], vf[db][2], vf[db][3]);
            }
#pragma unroll
            for (int db = 0; db < 4; db++) {
                mma16816(O[2*db],   pa[ks][0], pa[ks][1], pa[ks][2], pa[ks][3], vf[db][0], vf[db][1]);
                mma16816(O[2*db+1], pa[ks][0], pa[ks][1], pa[ks][2], pa[ks][3], vf[db][2], vf[db][3]);
            }
        }
        CP_WAIT1();
    }

    const float ig = 1.0f / gamma[0];
#pragma unroll
    for (int nt = 0; nt < 8; nt++) {
        int r = row0 + w * 16 + (lane >> 2);
        int col = h * HD_ + nt * 8 + (lane & 3) * 2;
        *(uint32_t*)&Cq[(size_t)r * HID_ + col]       = pack_h2(O[nt][0] * ig, O[nt][1] * ig);
        *(uint32_t*)&Cq[(size_t)(r + 8) * HID_ + col] = pack_h2(O[nt][2] * ig, O[nt][3] * ig);
    }
}

// ============================================================
// Launch
// ============================================================
extern "C" void kernel_launch(void* const* d_in, const int* in_sizes, int n_in,
                              void* d_out, int out_size)
{
    (void)in_sizes; (void)n_in; (void)out_size;
    const float* X    = (const float*)d_in[0];
    const float* mask = (const float*)d_in[1];
    const float* Wq   = (const float*)d_in[2];
    const float* bq   = (const float*)d_in[3];
    const float* Wk   = (const float*)d_in[4];
    const float* bk   = (const float*)d_in[5];
    const float* Wv   = (const float*)d_in[6];
    const float* bv   = (const float*)d_in[7];
    const float* Wo   = (const float*)d_in[8];
    const float* bo   = (const float*)d_in[9];
    const float* gamma = (const float*)d_in[11];   // beta (d_in[10]) cancels exactly
    float* out = (float*)d_out;

    __half *xh, *wh, *qp, *kp, *vp, *cp;
    float* mad;
    cudaGetSymbolAddress((void**)&xh,  g_Xh);
    cudaGetSymbolAddress((void**)&wh,  g_Wh);
    cudaGetSymbolAddress((void**)&qp,  g_Q);
    cudaGetSymbolAddress((void**)&kp,  g_K);
    cudaGetSymbolAddress((void**)&vp,  g_V);
    cudaGetSymbolAddress((void**)&cp,  g_C);
    cudaGetSymbolAddress((void**)&mad, g_Madd);

    cudaFuncSetAttribute(gemm_mma_f16<true>,  cudaFuncAttributeMaxDynamicSharedMemorySize, G_SMEM_B);
    cudaFuncSetAttribute(gemm_mma_f16<false>, cudaFuncAttributeMaxDynamicSharedMemorySize, G_SMEM_B);
    cudaFuncSetAttribute(consmax_attn_mma,    cudaFuncAttributeMaxDynamicSharedMemorySize, A_SMEM_B);

    const int NPREP = MTOT * HID_ / 4 + 4 * (WN_ / 4) + MTOT / 4;
    prep_all<<<(NPREP + 255) / 256, 256>>>(X, Wq, Wk, Wv, Wo, mask, xh, wh, mad);

    // fused QKV projection (1-term): z = 0(Q, x log2e/8), 1(K), 2(V)
    dim3 gq(HID_ / 128, MTOT / 128, 3);
    gemm_mma_f16<true><<<gq, 256, G_SMEM_B>>>(xh, wh,
                                              bq, bk, bv, nullptr,
                                              qp, kp, vp,
                                              MTOT, HID_, HID_, 0.125f * LOG2E);

    dim3 ga(S_ / 128, NH_, B_);        // (16, 16, 2)
    consmax_attn_mma<<<ga, 256, A_SMEM_B>>>(qp, kp, vp, mad, gamma, cp);

    // output projection (1-term, C single fp16) -> fp32 out
    dim3 go(HID_ / 128, MTOT / 128, 1);
    gemm_mma_f16<false><<<go, 256, G_SMEM_B>>>(cp, wh + 3 * (size_t)WN_,
                                               bo, nullptr, nullptr,
                                               out, nullptr, nullptr, nullptr,
                                               MTOT, HID_, HID_, 1.0f);
}